// round 2
// baseline (speedup 1.0000x reference)
#include <cuda_runtime.h>
#include <cuda_bf16.h>
#include <cstdint>
#include <cstddef>

#define B_ 32
#define N_ 512
#define H_ 8
#define RTOT (B_ * N_)   // 16384

// ----------------- static device scratch (no allocation) -----------------
__device__ float g_Wh [(size_t)RTOT * 512];   // layer1 Wh   [r][h*64+o]
__device__ float g_x  [(size_t)RTOT * 512];   // layer1 out  [r][h*64+o]
__device__ float g_Wh2[(size_t)RTOT * 64];    // layer2 Wh2  [r][o]
__device__ float g_z  [(size_t)RTOT * 64];    // layer2 out  [r][o]  (== z 32x32768)
__device__ float g_part[16 * 32 * 256];       // fc1 split-K partials
__device__ float g_z1 [32 * 256];
__device__ float g_z2 [32 * 256];

// ===================== GEMM1: state(16384x64) @ Wheads(64x512) =====================
__global__ __launch_bounds__(256) void gemm1_kernel(const float* __restrict__ A,
                                                    const float* __restrict__ W) {
    __shared__ float As[32][132];
    __shared__ float Bs[32][132];
    int tid = threadIdx.x;
    int c0 = blockIdx.x * 128;
    int m0 = blockIdx.y * 128;
    int tx = tid & 15, ty = tid >> 4;
    float acc[8][8];
#pragma unroll
    for (int i = 0; i < 8; i++)
#pragma unroll
        for (int j = 0; j < 8; j++) acc[i][j] = 0.f;

    for (int kc = 0; kc < 64; kc += 32) {
#pragma unroll
        for (int r = 0; r < 4; r++) {               // A chunk 128x32
            int idx = tid + r * 256;                // 0..1023
            int m = idx >> 3;
            int kg = (idx & 7) * 4;
            float4 v = *(const float4*)(A + (size_t)(m0 + m) * 64 + kc + kg);
            As[kg + 0][m] = v.x; As[kg + 1][m] = v.y;
            As[kg + 2][m] = v.z; As[kg + 3][m] = v.w;
        }
#pragma unroll
        for (int r = 0; r < 4; r++) {               // B chunk 32x128
            int idx = tid + r * 256;
            int k = idx >> 5;
            int n = (idx & 31) * 4;
            int col = c0 + n;
            int h = col >> 6, o = col & 63;
            float4 v = *(const float4*)(W + h * 4096 + (kc + k) * 64 + o);
            *(float4*)&Bs[k][n] = v;
        }
        __syncthreads();
#pragma unroll
        for (int k = 0; k < 32; k++) {
            float a[8], bb[8];
            *(float4*)&a[0]  = *(float4*)&As[k][ty * 8];
            *(float4*)&a[4]  = *(float4*)&As[k][ty * 8 + 4];
            *(float4*)&bb[0] = *(float4*)&Bs[k][tx * 8];
            *(float4*)&bb[4] = *(float4*)&Bs[k][tx * 8 + 4];
#pragma unroll
            for (int i = 0; i < 8; i++)
#pragma unroll
                for (int j = 0; j < 8; j++) acc[i][j] += a[i] * bb[j];
        }
        __syncthreads();
    }
#pragma unroll
    for (int i = 0; i < 8; i++) {
        float4 v0 = make_float4(acc[i][0], acc[i][1], acc[i][2], acc[i][3]);
        float4 v1 = make_float4(acc[i][4], acc[i][5], acc[i][6], acc[i][7]);
        float* p = g_Wh + (size_t)(m0 + ty * 8 + i) * 512 + c0 + tx * 8;
        *(float4*)p = v0;
        *(float4*)(p + 4) = v1;
    }
}

// ===================== GEMM2: g_x(16384x512) @ W_out(512x64) =====================
__global__ __launch_bounds__(256) void gemm2_kernel(const float* __restrict__ W) {
    __shared__ float As[32][132];
    __shared__ float Bs[32][68];
    int tid = threadIdx.x;
    int m0 = blockIdx.x * 128;
    int tx = tid & 15, ty = tid >> 4;   // cols tx*4, rows ty*8
    float acc[8][4];
#pragma unroll
    for (int i = 0; i < 8; i++)
#pragma unroll
        for (int j = 0; j < 4; j++) acc[i][j] = 0.f;

    for (int kc = 0; kc < 512; kc += 32) {
#pragma unroll
        for (int r = 0; r < 4; r++) {               // x chunk 128x32
            int idx = tid + r * 256;
            int m = idx >> 3;
            int kg = (idx & 7) * 4;
            float4 v = *(const float4*)(g_x + (size_t)(m0 + m) * 512 + kc + kg);
            As[kg + 0][m] = v.x; As[kg + 1][m] = v.y;
            As[kg + 2][m] = v.z; As[kg + 3][m] = v.w;
        }
#pragma unroll
        for (int r = 0; r < 2; r++) {               // W chunk 32x64
            int idx = tid + r * 256;                // 0..511
            int k = idx >> 4;
            int o = (idx & 15) * 4;
            *(float4*)&Bs[k][o] = *(const float4*)(W + (size_t)(kc + k) * 64 + o);
        }
        __syncthreads();
#pragma unroll
        for (int k = 0; k < 32; k++) {
            float a[8];
            *(float4*)&a[0] = *(float4*)&As[k][ty * 8];
            *(float4*)&a[4] = *(float4*)&As[k][ty * 8 + 4];
            float4 b4 = *(float4*)&Bs[k][tx * 4];
#pragma unroll
            for (int i = 0; i < 8; i++) {
                acc[i][0] += a[i] * b4.x; acc[i][1] += a[i] * b4.y;
                acc[i][2] += a[i] * b4.z; acc[i][3] += a[i] * b4.w;
            }
        }
        __syncthreads();
    }
#pragma unroll
    for (int i = 0; i < 8; i++) {
        float4 v = make_float4(acc[i][0], acc[i][1], acc[i][2], acc[i][3]);
        *(float4*)(g_Wh2 + (size_t)(m0 + ty * 8 + i) * 64 + tx * 4) = v;
    }
}

// ===================== factorized GAT attention =====================
// e[i,j] = leaky_relu(s_i + d_j): positive set is a suffix in d-sorted order.
// out_i = (c1*SufA(K) + c2*PreB(K)) / (c1*sufa(K) + c2*preb(K)),
// A_j = exp(d_j-dm), B_j = exp(0.2(d_j-dm)), t=s_i+dm, m=max(t,0.2t),
// c1=exp(t-m), c2=exp(0.2t-m). Max scaled weight == 1 exactly (stable).
__global__ __launch_bounds__(256) void attend_kernel(int layer,
                                                     const float* __restrict__ asrc,
                                                     const float* __restrict__ adst) {
    __shared__ float dv[512];
    __shared__ int   perm[512];
    __shared__ float ssrc[512];
    __shared__ float Ac[512];
    __shared__ float Bc[512];
    __shared__ float preB[65][65];
    __shared__ float sufA[65][65];
    __shared__ float prebS[65];
    __shared__ float sufaS[65];
    __shared__ float sAs[64], sAd[64];

    const float* Wh   = (layer == 1) ? g_Wh : g_Wh2;
    float*       outp = (layer == 1) ? g_x  : g_z;
    const int istride = (layer == 1) ? 512 : 64;
    const int ostride = istride;
    const int aStride = (layer == 1) ? 64 : 0;
    const int doElu   = (layer == 1) ? 1 : 0;

    int tid = threadIdx.x;
    int h = blockIdx.x, b = blockIdx.y;
    int icol0 = h * 64;
    const float* base = Wh + (size_t)b * 512 * istride + icol0;
    float* obase = outp + (size_t)b * 512 * ostride + icol0;

    if (tid < 64) { sAs[tid] = asrc[h * aStride + tid]; sAd[tid] = adst[h * aStride + tid]; }
    __syncthreads();

    int warp = tid >> 5, l = tid & 31;
    // per-row s_src / s_dst (warp per row-group, coalesced 64-wide rows)
    for (int n = warp * 64; n < warp * 64 + 64; n++) {
        const float* row = base + (size_t)n * istride;
        float v0 = row[l], v1 = row[l + 32];
        float ps = v0 * sAs[l] + v1 * sAs[l + 32];
        float pd = v0 * sAd[l] + v1 * sAd[l + 32];
#pragma unroll
        for (int off = 16; off; off >>= 1) {
            ps += __shfl_xor_sync(0xffffffffu, ps, off);
            pd += __shfl_xor_sync(0xffffffffu, pd, off);
        }
        if (l == 0) { ssrc[n] = ps; dv[n] = pd; perm[n] = n; }
    }
    __syncthreads();

    // bitonic sort ascending on dv (with perm)
    for (int k = 2; k <= 512; k <<= 1) {
        for (int j = k >> 1; j > 0; j >>= 1) {
#pragma unroll
            for (int r = 0; r < 2; r++) {
                int i = tid + r * 256;
                int ixj = i ^ j;
                if (ixj > i) {
                    bool up = ((i & k) == 0);
                    float a0 = dv[i], a1 = dv[ixj];
                    bool swap = up ? (a0 > a1) : (a0 < a1);
                    if (swap) {
                        dv[i] = a1; dv[ixj] = a0;
                        int p0 = perm[i]; perm[i] = perm[ixj]; perm[ixj] = p0;
                    }
                }
            }
            __syncthreads();
        }
    }

    float dm = dv[511];
    for (int r = tid; r < 512; r += 256) {
        float d = dv[r] - dm;
        Ac[r] = __expf(d);
        Bc[r] = __expf(0.2f * d);
    }
    if (tid < 64) { preB[0][tid] = 0.f; sufA[64][tid] = 0.f; }
    if (tid == 64) { prebS[0] = 0.f; sufaS[64] = 0.f; }
    __syncthreads();

    // chunk sums (C=8, 64 chunks)
    {
        int o = tid & 63;
        int cb = tid >> 6;
        for (int c = cb; c < 64; c += 4) {
            float sA = 0.f, sB = 0.f;
#pragma unroll
            for (int q = 0; q < 8; q++) {
                int j = c * 8 + q;
                float v = base[(size_t)perm[j] * istride + o];
                sA += Ac[j] * v;
                sB += Bc[j] * v;
            }
            sufA[c][o] = sA;
            preB[c + 1][o] = sB;
        }
        if (tid < 64) {
            int c = tid;
            float sa = 0.f, sb = 0.f;
#pragma unroll
            for (int q = 0; q < 8; q++) { sa += Ac[c * 8 + q]; sb += Bc[c * 8 + q]; }
            sufaS[c] = sa;
            prebS[c + 1] = sb;
        }
    }
    __syncthreads();
    // scans
    if (tid < 64) {
        int o = tid;
        for (int c = 1; c <= 64; c++) preB[c][o] += preB[c - 1][o];
    } else if (tid < 128) {
        int o = tid - 64;
        for (int c = 63; c >= 0; c--) sufA[c][o] += sufA[c + 1][o];
    } else if (tid == 128) {
        for (int c = 1; c <= 64; c++) prebS[c] += prebS[c - 1];
    } else if (tid == 129) {
        for (int c = 63; c >= 0; c--) sufaS[c] += sufaS[c + 1];
    }
    __syncthreads();

    // rows
    for (int n = warp * 64; n < warp * 64 + 64; n++) {
        float s = ssrc[n];
        float negs = -s;
        int lo = 0, hi = 512;
        while (lo < hi) { int mid = (lo + hi) >> 1; if (dv[mid] <= negs) lo = mid + 1; else hi = mid; }
        int K = lo;
        int cc = K >> 3;
        int ccp = (cc < 64) ? cc + 1 : 64;
        float t = s + dm;
        float m = fmaxf(t, 0.2f * t);
        float c1 = __expf(t - m), c2 = __expf(0.2f * t - m);

        float p0 = preB[cc][l],  p1 = preB[cc][l + 32];
        float s0 = sufA[ccp][l], s1 = sufA[ccp][l + 32];
        float pS = prebS[cc],    sS = sufaS[ccp];
#pragma unroll
        for (int q = 0; q < 8; q++) {
            int j = cc * 8 + q;
            if (j < 512) {
                float v0 = base[(size_t)perm[j] * istride + l];
                float v1 = base[(size_t)perm[j] * istride + l + 32];
                if (j < K) { p0 += Bc[j] * v0; p1 += Bc[j] * v1; pS += Bc[j]; }
                else       { s0 += Ac[j] * v0; s1 += Ac[j] * v1; sS += Ac[j]; }
            }
        }
        float inv = 1.f / (c1 * sS + c2 * pS);
        float r0 = (c1 * s0 + c2 * p0) * inv;
        float r1 = (c1 * s1 + c2 * p1) * inv;
        if (doElu) {
            r0 = (r0 > 0.f) ? r0 : (__expf(r0) - 1.f);
            r1 = (r1 > 0.f) ? r1 : (__expf(r1) - 1.f);
        }
        obase[(size_t)n * ostride + l] = r0;
        obase[(size_t)n * ostride + l + 32] = r1;
    }
}

// ===================== fc1: z(32x32768) @ fc1_w(32768x256), split-K =====================
__global__ __launch_bounds__(256) void fc1_partial_kernel(const float* __restrict__ w) {
    __shared__ float zs[32][136];
    int tid = threadIdx.x;
    int c0 = blockIdx.x * 64;
    int k0 = blockIdx.y * 2048;
    int c = tid & 63, rq = tid >> 6;
    float acc[8];
#pragma unroll
    for (int i = 0; i < 8; i++) acc[i] = 0.f;

    for (int sub = 0; sub < 16; sub++) {
        int kb = k0 + sub * 128;
#pragma unroll
        for (int r = 0; r < 4; r++) {
            int idx = tid + r * 256;             // 1024 float4 slots = 32x128
            int row = idx >> 5;
            int kk = (idx & 31) * 4;
            *(float4*)&zs[row][kk] = *(const float4*)(g_z + (size_t)row * 32768 + kb + kk);
        }
        __syncthreads();
        for (int kk = 0; kk < 128; kk += 4) {
            float w0 = w[(size_t)(kb + kk + 0) * 256 + c0 + c];
            float w1 = w[(size_t)(kb + kk + 1) * 256 + c0 + c];
            float w2 = w[(size_t)(kb + kk + 2) * 256 + c0 + c];
            float w3 = w[(size_t)(kb + kk + 3) * 256 + c0 + c];
#pragma unroll
            for (int r8 = 0; r8 < 8; r8++) {
                float4 zv = *(float4*)&zs[rq * 8 + r8][kk];
                acc[r8] += zv.x * w0 + zv.y * w1 + zv.z * w2 + zv.w * w3;
            }
        }
        __syncthreads();
    }
#pragma unroll
    for (int r8 = 0; r8 < 8; r8++)
        g_part[(size_t)blockIdx.y * 8192 + (rq * 8 + r8) * 256 + c0 + c] = acc[r8];
}

__global__ void fc1_reduce_kernel(const float* __restrict__ bias) {
    int idx = blockIdx.x * 256 + threadIdx.x;   // 0..8191
    float s = bias[idx & 255];
    for (int q = 0; q < 16; q++) s += g_part[q * 8192 + idx];
    g_z1[idx] = fmaxf(s, 0.f);
}

__global__ __launch_bounds__(256) void fc2_kernel(const float* __restrict__ w,
                                                  const float* __restrict__ bias) {
    __shared__ float zs[32 * 260];
    int tid = threadIdx.x;
    for (int i = tid; i < 8192; i += 256) zs[(i >> 8) * 260 + (i & 255)] = g_z1[i];
    __syncthreads();
    int c = blockIdx.x * 8 + (tid & 7);
    int r = tid >> 3;
    float acc = bias[c];
#pragma unroll 8
    for (int k = 0; k < 256; k++) acc += zs[r * 260 + k] * w[k * 256 + c];
    g_z2[r * 256 + c] = fmaxf(acc, 0.f);
}

__global__ void fc3_kernel(const float* __restrict__ w, const float* __restrict__ bias,
                           float* __restrict__ outp) {
    int tid = threadIdx.x;       // 128 threads = 32 rows x 4 actions
    int r = tid >> 2, a = tid & 3;
    float acc = bias[a];
#pragma unroll 8
    for (int k = 0; k < 256; k++) acc += g_z2[r * 256 + k] * w[k * 4 + a];
    outp[r * 4 + a] = tanhf(acc);   // MAX_ACTION = 1.0
}

// ===================== launch =====================
extern "C" void kernel_launch(void* const* d_in, const int* in_sizes, int n_in,
                              void* d_out, int out_size) {
    const float* state     = (const float*)d_in[0];
    const float* W_heads   = (const float*)d_in[1];
    const float* a_src     = (const float*)d_in[2];
    const float* a_dst     = (const float*)d_in[3];
    const float* W_out     = (const float*)d_in[4];
    const float* a_out_src = (const float*)d_in[5];
    const float* a_out_dst = (const float*)d_in[6];
    const float* fc1_w     = (const float*)d_in[7];
    const float* fc1_b     = (const float*)d_in[8];
    const float* fc2_w     = (const float*)d_in[9];
    const float* fc2_b     = (const float*)d_in[10];
    const float* fc3_w     = (const float*)d_in[11];
    const float* fc3_b     = (const float*)d_in[12];
    float* out = (float*)d_out;

    gemm1_kernel<<<dim3(4, 128), 256>>>(state, W_heads);
    attend_kernel<<<dim3(8, 32), 256>>>(1, a_src, a_dst);
    gemm2_kernel<<<128, 256>>>(W_out);
    attend_kernel<<<dim3(1, 32), 256>>>(2, a_out_src, a_out_dst);
    fc1_partial_kernel<<<dim3(4, 16), 256>>>(fc1_w);
    fc1_reduce_kernel<<<32, 256>>>(fc1_b);
    fc2_kernel<<<32, 256>>>(fc2_w, fc2_b);
    fc3_kernel<<<1, 128>>>(fc3_w, fc3_b, out);
}

// round 3
// speedup vs baseline: 1.7970x; 1.7970x over previous
#include <cuda_runtime.h>
#include <cuda_bf16.h>
#include <cstdint>
#include <cstddef>

#define B_ 32
#define N_ 512
#define H_ 8
#define RTOT (B_ * N_)   // 16384

// ----------------- static device scratch (no allocation) -----------------
__device__ float g_Wh [(size_t)RTOT * 512];   // layer1 Wh   [r][h*64+o]
__device__ float g_x  [(size_t)RTOT * 512];   // layer1 out  [r][h*64+o]
__device__ float g_Wh2[(size_t)RTOT * 64];    // layer2 Wh2  [r][o]
__device__ float g_z  [(size_t)RTOT * 64];    // layer2 out  [r][o]  (== z 32x32768)
__device__ float g_part[32 * 32 * 256];       // fc1 split-K partials
__device__ float g_z1 [32 * 256];
__device__ float g_z2 [32 * 256];

// ===================== GEMM1: state(16384x64) @ Wheads(64x512) =====================
__global__ __launch_bounds__(256) void gemm1_kernel(const float* __restrict__ A,
                                                    const float* __restrict__ W) {
    __shared__ float As[32][132];
    __shared__ float Bs[32][132];
    int tid = threadIdx.x;
    int c0 = blockIdx.x * 128;
    int m0 = blockIdx.y * 128;
    int tx = tid & 15, ty = tid >> 4;
    float acc[8][8];
#pragma unroll
    for (int i = 0; i < 8; i++)
#pragma unroll
        for (int j = 0; j < 8; j++) acc[i][j] = 0.f;

    for (int kc = 0; kc < 64; kc += 32) {
#pragma unroll
        for (int r = 0; r < 4; r++) {               // A chunk 128x32
            int idx = tid + r * 256;                // 0..1023
            int m = idx >> 3;
            int kg = (idx & 7) * 4;
            float4 v = *(const float4*)(A + (size_t)(m0 + m) * 64 + kc + kg);
            As[kg + 0][m] = v.x; As[kg + 1][m] = v.y;
            As[kg + 2][m] = v.z; As[kg + 3][m] = v.w;
        }
#pragma unroll
        for (int r = 0; r < 4; r++) {               // B chunk 32x128
            int idx = tid + r * 256;
            int k = idx >> 5;
            int n = (idx & 31) * 4;
            int col = c0 + n;
            int h = col >> 6, o = col & 63;
            float4 v = *(const float4*)(W + h * 4096 + (kc + k) * 64 + o);
            *(float4*)&Bs[k][n] = v;
        }
        __syncthreads();
#pragma unroll
        for (int k = 0; k < 32; k++) {
            float a[8], bb[8];
            *(float4*)&a[0]  = *(float4*)&As[k][ty * 8];
            *(float4*)&a[4]  = *(float4*)&As[k][ty * 8 + 4];
            *(float4*)&bb[0] = *(float4*)&Bs[k][tx * 8];
            *(float4*)&bb[4] = *(float4*)&Bs[k][tx * 8 + 4];
#pragma unroll
            for (int i = 0; i < 8; i++)
#pragma unroll
                for (int j = 0; j < 8; j++) acc[i][j] += a[i] * bb[j];
        }
        __syncthreads();
    }
#pragma unroll
    for (int i = 0; i < 8; i++) {
        float4 v0 = make_float4(acc[i][0], acc[i][1], acc[i][2], acc[i][3]);
        float4 v1 = make_float4(acc[i][4], acc[i][5], acc[i][6], acc[i][7]);
        float* p = g_Wh + (size_t)(m0 + ty * 8 + i) * 512 + c0 + tx * 8;
        *(float4*)p = v0;
        *(float4*)(p + 4) = v1;
    }
}

// ===================== GEMM2: g_x(16384x512) @ W_out(512x64) =====================
__global__ __launch_bounds__(256) void gemm2_kernel(const float* __restrict__ W) {
    __shared__ float As[32][132];
    __shared__ float Bs[32][68];
    int tid = threadIdx.x;
    int m0 = blockIdx.x * 128;
    int tx = tid & 15, ty = tid >> 4;   // cols tx*4, rows ty*8
    float acc[8][4];
#pragma unroll
    for (int i = 0; i < 8; i++)
#pragma unroll
        for (int j = 0; j < 4; j++) acc[i][j] = 0.f;

    for (int kc = 0; kc < 512; kc += 32) {
#pragma unroll
        for (int r = 0; r < 4; r++) {               // x chunk 128x32
            int idx = tid + r * 256;
            int m = idx >> 3;
            int kg = (idx & 7) * 4;
            float4 v = *(const float4*)(g_x + (size_t)(m0 + m) * 512 + kc + kg);
            As[kg + 0][m] = v.x; As[kg + 1][m] = v.y;
            As[kg + 2][m] = v.z; As[kg + 3][m] = v.w;
        }
#pragma unroll
        for (int r = 0; r < 2; r++) {               // W chunk 32x64
            int idx = tid + r * 256;                // 0..511
            int k = idx >> 4;
            int o = (idx & 15) * 4;
            *(float4*)&Bs[k][o] = *(const float4*)(W + (size_t)(kc + k) * 64 + o);
        }
        __syncthreads();
#pragma unroll
        for (int k = 0; k < 32; k++) {
            float a[8];
            *(float4*)&a[0] = *(float4*)&As[k][ty * 8];
            *(float4*)&a[4] = *(float4*)&As[k][ty * 8 + 4];
            float4 b4 = *(float4*)&Bs[k][tx * 4];
#pragma unroll
            for (int i = 0; i < 8; i++) {
                acc[i][0] += a[i] * b4.x; acc[i][1] += a[i] * b4.y;
                acc[i][2] += a[i] * b4.z; acc[i][3] += a[i] * b4.w;
            }
        }
        __syncthreads();
    }
#pragma unroll
    for (int i = 0; i < 8; i++) {
        float4 v = make_float4(acc[i][0], acc[i][1], acc[i][2], acc[i][3]);
        *(float4*)(g_Wh2 + (size_t)(m0 + ty * 8 + i) * 64 + tx * 4) = v;
    }
}

// ===================== factorized GAT attention (512 threads, row-split) =====================
// e[i,j] = leaky_relu(s_i + d_j): positive set is a suffix in d-sorted order.
// out_i = (c1*SufA(K) + c2*PreB(K)) / (c1*sufa(K) + c2*preb(K)),
// A_j = exp(d_j-dm), B_j = exp(0.2(d_j-dm)), t=s_i+dm, m=max(t,0.2t),
// c1=exp(t-m), c2=exp(0.2t-m).  Column 64 of the tables carries the scalar sums.
__global__ __launch_bounds__(512) void attend_kernel(int layer, int rowsPerBlock,
                                                     const float* __restrict__ asrc,
                                                     const float* __restrict__ adst) {
    __shared__ float dv[512];
    __shared__ int   perm[512];
    __shared__ float ssrc[512];
    __shared__ float preB[65][66];   // [c][o], o=0..63 cols, o=64 scalar
    __shared__ float sufA[65][66];
    __shared__ float gsum[8][66];
    __shared__ float sAs[64], sAd[64];
    __shared__ int   Kv[256];

    const float* Wh   = (layer == 1) ? g_Wh : g_Wh2;
    float*       outp = (layer == 1) ? g_x  : g_z;
    const int istride = (layer == 1) ? 512 : 64;
    const int aStride = (layer == 1) ? 64 : 0;
    const int doElu   = (layer == 1) ? 1 : 0;

    int tid = threadIdx.x;
    int h = blockIdx.x, b = blockIdx.y;
    int rStart = blockIdx.z * rowsPerBlock;
    const float* base = Wh + (size_t)b * 512 * istride + h * 64;
    float* obase = outp + (size_t)b * 512 * istride + h * 64;

    if (tid < 64) { sAs[tid] = asrc[h * aStride + tid]; sAd[tid] = adst[h * aStride + tid]; }
    __syncthreads();

    int warp = tid >> 5, l = tid & 31;
    // s_src / d for ALL 512 rows (16 warps x 32 rows)
    for (int n = warp * 32; n < warp * 32 + 32; n++) {
        const float* row = base + (size_t)n * istride;
        float v0 = row[l], v1 = row[l + 32];
        float ps = v0 * sAs[l] + v1 * sAs[l + 32];
        float pd = v0 * sAd[l] + v1 * sAd[l + 32];
#pragma unroll
        for (int off = 16; off; off >>= 1) {
            ps += __shfl_xor_sync(0xffffffffu, ps, off);
            pd += __shfl_xor_sync(0xffffffffu, pd, off);
        }
        if (l == 0) { ssrc[n] = ps; dv[n] = pd; perm[n] = n; }
    }
    __syncthreads();

    // bitonic sort ascending on dv (with perm), 1 element per thread
    for (int k = 2; k <= 512; k <<= 1) {
        for (int j = k >> 1; j > 0; j >>= 1) {
            int i = tid;
            int ixj = i ^ j;
            if (ixj > i) {
                bool up = ((i & k) == 0);
                float a0 = dv[i], a1 = dv[ixj];
                bool swap = up ? (a0 > a1) : (a0 < a1);
                if (swap) {
                    dv[i] = a1; dv[ixj] = a0;
                    int p0 = perm[i]; perm[i] = perm[ixj]; perm[ixj] = p0;
                }
            }
            __syncthreads();
        }
    }

    float dm = dv[511];

    if (tid < 65) { preB[0][tid] = 0.f; sufA[64][tid] = 0.f; }
    // raw chunk sums (64 chunks of 8, 65 "columns")
    for (int it = tid; it < 64 * 65; it += 512) {
        int c = it / 65;
        int o = it - c * 65;
        float sA = 0.f, sB = 0.f;
#pragma unroll
        for (int q = 0; q < 8; q++) {
            int j = c * 8 + q;
            float d = dv[j] - dm;
            float a = __expf(d);
            float bw = __expf(0.2f * d);
            float v = (o < 64) ? base[(size_t)perm[j] * istride + o] : 1.0f;
            sA += a * v;
            sB += bw * v;
        }
        sufA[c][o] = sA;
        preB[c + 1][o] = sB;
    }
    __syncthreads();

    // ---- two-level prefix scan of preB over c = 1..64 ----
    for (int it = tid; it < 8 * 65; it += 512) {
        int g = it / 65, o = it - g * 65;
        float run = 0.f;
#pragma unroll
        for (int k2 = 0; k2 < 8; k2++) {
            int c = g * 8 + 1 + k2;
            run += preB[c][o];
            preB[c][o] = run;
        }
        gsum[g][o] = run;
    }
    __syncthreads();
    if (tid < 65) {
        int o = tid;
        float run = 0.f;
#pragma unroll
        for (int g = 0; g < 8; g++) { float t = gsum[g][o]; gsum[g][o] = run; run += t; }
    }
    __syncthreads();
    for (int it = tid; it < 8 * 65; it += 512) {
        int g = it / 65, o = it - g * 65;
        float add = gsum[g][o];
#pragma unroll
        for (int k2 = 0; k2 < 8; k2++) preB[g * 8 + 1 + k2][o] += add;
    }
    __syncthreads();

    // ---- two-level suffix scan of sufA over c = 63..0 ----
    for (int it = tid; it < 8 * 65; it += 512) {
        int g = it / 65, o = it - g * 65;
        float run = 0.f;
#pragma unroll
        for (int k2 = 7; k2 >= 0; k2--) {
            int c = g * 8 + k2;
            run += sufA[c][o];
            sufA[c][o] = run;
        }
        gsum[g][o] = run;
    }
    __syncthreads();
    if (tid < 65) {
        int o = tid;
        float run = 0.f;
#pragma unroll
        for (int g = 7; g >= 0; g--) { float t = gsum[g][o]; gsum[g][o] = run; run += t; }
    }
    __syncthreads();
    for (int it = tid; it < 8 * 65; it += 512) {
        int g = it / 65, o = it - g * 65;
        float add = gsum[g][o];
#pragma unroll
        for (int k2 = 0; k2 < 8; k2++) sufA[g * 8 + k2][o] += add;
    }
    __syncthreads();

    // parallel binary searches for this block's row slice
    if (tid < rowsPerBlock) {
        float negs = -ssrc[rStart + tid];
        int lo = 0, hi = 512;
        while (lo < hi) { int mid = (lo + hi) >> 1; if (dv[mid] <= negs) lo = mid + 1; else hi = mid; }
        Kv[tid] = lo;
    }
    __syncthreads();

    // row outputs: warp per row, strided
    for (int ni = warp; ni < rowsPerBlock; ni += 16) {
        int n = rStart + ni;
        int K = Kv[ni];
        int cc = K >> 3;
        int ccp = (cc < 64) ? cc + 1 : 64;
        float t = ssrc[n] + dm;
        float m = fmaxf(t, 0.2f * t);
        float c1 = __expf(t - m), c2 = __expf(0.2f * t - m);

        float p0 = preB[cc][l],  p1 = preB[cc][l + 32],  pS = preB[cc][64];
        float s0 = sufA[ccp][l], s1 = sufA[ccp][l + 32], sS = sufA[ccp][64];
#pragma unroll
        for (int q = 0; q < 8; q++) {
            int j = cc * 8 + q;
            if (j < 512) {
                float d = dv[j] - dm;
                const float* prow = base + (size_t)perm[j] * istride;
                float v0 = prow[l], v1 = prow[l + 32];
                if (j < K) {
                    float w = __expf(0.2f * d);
                    p0 += w * v0; p1 += w * v1; pS += w;
                } else {
                    float w = __expf(d);
                    s0 += w * v0; s1 += w * v1; sS += w;
                }
            }
        }
        float inv = 1.f / (c1 * sS + c2 * pS);
        float r0 = (c1 * s0 + c2 * p0) * inv;
        float r1 = (c1 * s1 + c2 * p1) * inv;
        if (doElu) {
            r0 = (r0 > 0.f) ? r0 : (__expf(r0) - 1.f);
            r1 = (r1 > 0.f) ? r1 : (__expf(r1) - 1.f);
        }
        obase[(size_t)n * istride + l] = r0;
        obase[(size_t)n * istride + l + 32] = r1;
    }
}

// ===================== fc1: z(32x32768) @ fc1_w(32768x256), split-K x32 =====================
__global__ __launch_bounds__(256) void fc1_partial_kernel(const float* __restrict__ w) {
    __shared__ float zs[32][136];
    int tid = threadIdx.x;
    int c0 = blockIdx.x * 64;
    int k0 = blockIdx.y * 1024;
    int c = tid & 63, rq = tid >> 6;
    float acc[8];
#pragma unroll
    for (int i = 0; i < 8; i++) acc[i] = 0.f;

    for (int sub = 0; sub < 8; sub++) {
        int kb = k0 + sub * 128;
#pragma unroll
        for (int r = 0; r < 4; r++) {
            int idx = tid + r * 256;             // 1024 float4 slots = 32x128
            int row = idx >> 5;
            int kk = (idx & 31) * 4;
            *(float4*)&zs[row][kk] = *(const float4*)(g_z + (size_t)row * 32768 + kb + kk);
        }
        __syncthreads();
        for (int kk = 0; kk < 128; kk += 4) {
            float w0 = w[(size_t)(kb + kk + 0) * 256 + c0 + c];
            float w1 = w[(size_t)(kb + kk + 1) * 256 + c0 + c];
            float w2 = w[(size_t)(kb + kk + 2) * 256 + c0 + c];
            float w3 = w[(size_t)(kb + kk + 3) * 256 + c0 + c];
#pragma unroll
            for (int r8 = 0; r8 < 8; r8++) {
                float4 zv = *(float4*)&zs[rq * 8 + r8][kk];
                acc[r8] += zv.x * w0 + zv.y * w1 + zv.z * w2 + zv.w * w3;
            }
        }
        __syncthreads();
    }
#pragma unroll
    for (int r8 = 0; r8 < 8; r8++)
        g_part[(size_t)blockIdx.y * 8192 + (rq * 8 + r8) * 256 + c0 + c] = acc[r8];
}

__global__ void fc1_reduce_kernel(const float* __restrict__ bias) {
    int idx = blockIdx.x * 256 + threadIdx.x;   // 0..8191
    float s = bias[idx & 255];
    for (int q = 0; q < 32; q++) s += g_part[q * 8192 + idx];
    g_z1[idx] = fmaxf(s, 0.f);
}

__global__ __launch_bounds__(256) void fc2_kernel(const float* __restrict__ w,
                                                  const float* __restrict__ bias) {
    __shared__ float zs[32 * 260];
    int tid = threadIdx.x;
    for (int i = tid; i < 8192; i += 256) zs[(i >> 8) * 260 + (i & 255)] = g_z1[i];
    __syncthreads();
    int c = blockIdx.x * 8 + (tid & 7);
    int r = tid >> 3;
    float acc = bias[c];
#pragma unroll 8
    for (int k = 0; k < 256; k++) acc += zs[r * 260 + k] * w[k * 256 + c];
    g_z2[r * 256 + c] = fmaxf(acc, 0.f);
}

__global__ void fc3_kernel(const float* __restrict__ w, const float* __restrict__ bias,
                           float* __restrict__ outp) {
    int tid = threadIdx.x;       // 128 threads = 32 rows x 4 actions
    int r = tid >> 2, a = tid & 3;
    float acc = bias[a];
#pragma unroll 8
    for (int k = 0; k < 256; k++) acc += g_z2[r * 256 + k] * w[k * 4 + a];
    outp[r * 4 + a] = tanhf(acc);   // MAX_ACTION = 1.0
}

// ===================== launch =====================
extern "C" void kernel_launch(void* const* d_in, const int* in_sizes, int n_in,
                              void* d_out, int out_size) {
    const float* state     = (const float*)d_in[0];
    const float* W_heads   = (const float*)d_in[1];
    const float* a_src     = (const float*)d_in[2];
    const float* a_dst     = (const float*)d_in[3];
    const float* W_out     = (const float*)d_in[4];
    const float* a_out_src = (const float*)d_in[5];
    const float* a_out_dst = (const float*)d_in[6];
    const float* fc1_w     = (const float*)d_in[7];
    const float* fc1_b     = (const float*)d_in[8];
    const float* fc2_w     = (const float*)d_in[9];
    const float* fc2_b     = (const float*)d_in[10];
    const float* fc3_w     = (const float*)d_in[11];
    const float* fc3_b     = (const float*)d_in[12];
    float* out = (float*)d_out;

    gemm1_kernel<<<dim3(4, 128), 256>>>(state, W_heads);
    attend_kernel<<<dim3(8, 32, 2), 512>>>(1, 256, a_src, a_dst);      // 512 blocks
    gemm2_kernel<<<128, 256>>>(W_out);
    attend_kernel<<<dim3(1, 32, 4), 512>>>(2, 128, a_out_src, a_out_dst); // 128 blocks
    fc1_partial_kernel<<<dim3(4, 32), 256>>>(fc1_w);
    fc1_reduce_kernel<<<32, 256>>>(fc1_b);
    fc2_kernel<<<32, 256>>>(fc2_w, fc2_b);
    fc3_kernel<<<1, 128>>>(fc3_w, fc3_b, out);
}

// round 5
// speedup vs baseline: 2.3222x; 1.2922x over previous
#include <cuda_runtime.h>
#include <cuda_bf16.h>
#include <cstdint>
#include <cstddef>

#define B_ 32
#define N_ 512
#define H_ 8
#define RTOT (B_ * N_)   // 16384

// ----------------- static device scratch (no allocation) -----------------
__device__ float g_Wh [(size_t)RTOT * 512];   // layer1 Wh   [r][h*64+o]
__device__ float g_x  [(size_t)RTOT * 512];   // layer1 out  [r][h*64+o]
__device__ float g_Wh2[(size_t)RTOT * 64];    // layer2 Wh2  [r][o]
__device__ float g_z  [(size_t)RTOT * 64];    // layer2 out  [r][o]  (== z 32x32768)
__device__ float g_part[64 * 32 * 256];       // fc1 split-K partials
__device__ float g_z1 [32 * 256];
__device__ float g_z2 [32 * 256];

// ----------------- mma helpers -----------------
__device__ __forceinline__ void mma_bf16(float* c, uint32_t a0, uint32_t a1,
                                         uint32_t a2, uint32_t a3,
                                         uint32_t b0, uint32_t b1) {
    asm volatile(
        "mma.sync.aligned.m16n8k16.row.col.f32.bf16.bf16.f32 "
        "{%0,%1,%2,%3}, {%4,%5,%6,%7}, {%8,%9}, {%0,%1,%2,%3};\n"
        : "+f"(c[0]), "+f"(c[1]), "+f"(c[2]), "+f"(c[3])
        : "r"(a0), "r"(a1), "r"(a2), "r"(a3), "r"(b0), "r"(b1));
}

__device__ __forceinline__ void split_bf16(float x, __nv_bfloat16& h, __nv_bfloat16& l) {
    h = __float2bfloat16(x);
    l = __float2bfloat16(x - __bfloat162float(h));
}

// ===================== GEMM1 (mma): state(16384x64) @ Wheads(64x512) -> g_Wh =====================
__global__ __launch_bounds__(256) void gemm1_mma(const float* __restrict__ A,
                                                 const float* __restrict__ W) {
    __shared__ __align__(16) __nv_bfloat16 Ah[128][40], Al[128][40];
    __shared__ __align__(16) __nv_bfloat16 Bh[128][40], Bl[128][40];
    int tid = threadIdx.x;
    int c0 = blockIdx.x * 128;
    int m0 = blockIdx.y * 128;
    int w = tid >> 5, lane = tid & 31;
    int g = lane >> 2, tig = lane & 3;
    int wm = w & 3, wn = w >> 2;          // warp tile: rows wm*32, cols wn*64

    float acc[2][8][4];
#pragma unroll
    for (int a = 0; a < 2; a++)
#pragma unroll
        for (int b = 0; b < 8; b++)
#pragma unroll
            for (int c = 0; c < 4; c++) acc[a][b][c] = 0.f;

    for (int kc = 0; kc < 64; kc += 32) {
        if (kc) __syncthreads();
        // A chunk 128x32 fp32 -> split bf16
#pragma unroll
        for (int r = 0; r < 4; r++) {
            int idx = tid + r * 256;
            int m = idx >> 3, kg = (idx & 7) * 4;
            float4 v = *(const float4*)(A + (size_t)(m0 + m) * 64 + kc + kg);
            split_bf16(v.x, Ah[m][kg + 0], Al[m][kg + 0]);
            split_bf16(v.y, Ah[m][kg + 1], Al[m][kg + 1]);
            split_bf16(v.z, Ah[m][kg + 2], Al[m][kg + 2]);
            split_bf16(v.w, Ah[m][kg + 3], Al[m][kg + 3]);
        }
        // B chunk 32x128 -> transposed split bf16 (Bs[n][k])
#pragma unroll
        for (int r = 0; r < 4; r++) {
            int idx = tid + r * 256;
            int k = idx >> 5, c4 = (idx & 31) * 4;
            int col = c0 + c4;
            int h = col >> 6, o = col & 63;
            float4 v = *(const float4*)(W + h * 4096 + (kc + k) * 64 + o);
            split_bf16(v.x, Bh[c4 + 0][k], Bl[c4 + 0][k]);
            split_bf16(v.y, Bh[c4 + 1][k], Bl[c4 + 1][k]);
            split_bf16(v.z, Bh[c4 + 2][k], Bl[c4 + 2][k]);
            split_bf16(v.w, Bh[c4 + 3][k], Bl[c4 + 3][k]);
        }
        __syncthreads();

#pragma unroll
        for (int ks = 0; ks < 32; ks += 16) {
            uint32_t ah[2][4], al[2][4];
            int cA = ks + 2 * tig;
#pragma unroll
            for (int tm = 0; tm < 2; tm++) {
                int r0 = wm * 32 + tm * 16 + g;
                ah[tm][0] = *(uint32_t*)&Ah[r0][cA];
                ah[tm][1] = *(uint32_t*)&Ah[r0 + 8][cA];
                ah[tm][2] = *(uint32_t*)&Ah[r0][cA + 8];
                ah[tm][3] = *(uint32_t*)&Ah[r0 + 8][cA + 8];
                al[tm][0] = *(uint32_t*)&Al[r0][cA];
                al[tm][1] = *(uint32_t*)&Al[r0 + 8][cA];
                al[tm][2] = *(uint32_t*)&Al[r0][cA + 8];
                al[tm][3] = *(uint32_t*)&Al[r0 + 8][cA + 8];
            }
#pragma unroll
            for (int tn = 0; tn < 8; tn++) {
                int n = wn * 64 + tn * 8 + g;
                uint32_t bh0 = *(uint32_t*)&Bh[n][cA], bh1 = *(uint32_t*)&Bh[n][cA + 8];
                uint32_t bl0 = *(uint32_t*)&Bl[n][cA], bl1 = *(uint32_t*)&Bl[n][cA + 8];
#pragma unroll
                for (int tm = 0; tm < 2; tm++) {
                    mma_bf16(acc[tm][tn], ah[tm][0], ah[tm][1], ah[tm][2], ah[tm][3], bh0, bh1);
                    mma_bf16(acc[tm][tn], ah[tm][0], ah[tm][1], ah[tm][2], ah[tm][3], bl0, bl1);
                    mma_bf16(acc[tm][tn], al[tm][0], al[tm][1], al[tm][2], al[tm][3], bh0, bh1);
                }
            }
        }
    }
#pragma unroll
    for (int tm = 0; tm < 2; tm++)
#pragma unroll
        for (int tn = 0; tn < 8; tn++) {
            int r0 = m0 + wm * 32 + tm * 16 + g;
            int c = c0 + wn * 64 + tn * 8 + 2 * tig;
            float2 v0 = make_float2(acc[tm][tn][0], acc[tm][tn][1]);
            float2 v1 = make_float2(acc[tm][tn][2], acc[tm][tn][3]);
            *(float2*)&g_Wh[(size_t)r0 * 512 + c] = v0;
            *(float2*)&g_Wh[(size_t)(r0 + 8) * 512 + c] = v1;
        }
}

// ===================== GEMM2 (mma): g_x(16384x512) @ W_out(512x64) -> g_Wh2 =====================
__global__ __launch_bounds__(256) void gemm2_mma(const float* __restrict__ W) {
    __shared__ __align__(16) __nv_bfloat16 Ah[128][40], Al[128][40];
    __shared__ __align__(16) __nv_bfloat16 Bh[64][40], Bl[64][40];
    int tid = threadIdx.x;
    int m0 = blockIdx.x * 128;
    int w = tid >> 5, lane = tid & 31;
    int g = lane >> 2, tig = lane & 3;

    float acc[8][4];
#pragma unroll
    for (int b = 0; b < 8; b++)
#pragma unroll
        for (int c = 0; c < 4; c++) acc[b][c] = 0.f;

    for (int kc = 0; kc < 512; kc += 32) {
        if (kc) __syncthreads();
#pragma unroll
        for (int r = 0; r < 4; r++) {
            int idx = tid + r * 256;
            int m = idx >> 3, kg = (idx & 7) * 4;
            float4 v = *(const float4*)(g_x + (size_t)(m0 + m) * 512 + kc + kg);
            split_bf16(v.x, Ah[m][kg + 0], Al[m][kg + 0]);
            split_bf16(v.y, Ah[m][kg + 1], Al[m][kg + 1]);
            split_bf16(v.z, Ah[m][kg + 2], Al[m][kg + 2]);
            split_bf16(v.w, Ah[m][kg + 3], Al[m][kg + 3]);
        }
#pragma unroll
        for (int r = 0; r < 2; r++) {
            int idx = tid + r * 256;
            int k = idx >> 4, o4 = (idx & 15) * 4;
            float4 v = *(const float4*)(W + (size_t)(kc + k) * 64 + o4);
            split_bf16(v.x, Bh[o4 + 0][k], Bl[o4 + 0][k]);
            split_bf16(v.y, Bh[o4 + 1][k], Bl[o4 + 1][k]);
            split_bf16(v.z, Bh[o4 + 2][k], Bl[o4 + 2][k]);
            split_bf16(v.w, Bh[o4 + 3][k], Bl[o4 + 3][k]);
        }
        __syncthreads();

#pragma unroll
        for (int ks = 0; ks < 32; ks += 16) {
            int cA = ks + 2 * tig;
            int r0 = w * 16 + g;
            uint32_t ah0 = *(uint32_t*)&Ah[r0][cA],     ah1 = *(uint32_t*)&Ah[r0 + 8][cA];
            uint32_t ah2 = *(uint32_t*)&Ah[r0][cA + 8], ah3 = *(uint32_t*)&Ah[r0 + 8][cA + 8];
            uint32_t al0 = *(uint32_t*)&Al[r0][cA],     al1 = *(uint32_t*)&Al[r0 + 8][cA];
            uint32_t al2 = *(uint32_t*)&Al[r0][cA + 8], al3 = *(uint32_t*)&Al[r0 + 8][cA + 8];
#pragma unroll
            for (int tn = 0; tn < 8; tn++) {
                int n = tn * 8 + g;
                uint32_t bh0 = *(uint32_t*)&Bh[n][cA], bh1 = *(uint32_t*)&Bh[n][cA + 8];
                uint32_t bl0 = *(uint32_t*)&Bl[n][cA], bl1 = *(uint32_t*)&Bl[n][cA + 8];
                mma_bf16(acc[tn], ah0, ah1, ah2, ah3, bh0, bh1);
                mma_bf16(acc[tn], ah0, ah1, ah2, ah3, bl0, bl1);
                mma_bf16(acc[tn], al0, al1, al2, al3, bh0, bh1);
            }
        }
    }
#pragma unroll
    for (int tn = 0; tn < 8; tn++) {
        int r0 = m0 + w * 16 + g;
        int c = tn * 8 + 2 * tig;
        *(float2*)&g_Wh2[(size_t)r0 * 64 + c] = make_float2(acc[tn][0], acc[tn][1]);
        *(float2*)&g_Wh2[(size_t)(r0 + 8) * 64 + c] = make_float2(acc[tn][2], acc[tn][3]);
    }
}

// ===================== factorized GAT attention (512 threads, row-split) =====================
__global__ __launch_bounds__(512) void attend_kernel(int layer, int rowsPerBlock,
                                                     const float* __restrict__ asrc,
                                                     const float* __restrict__ adst) {
    __shared__ float dv[512];
    __shared__ int   perm[512];
    __shared__ float ssrc[512];
    __shared__ float Ac[512];
    __shared__ float Bc[512];
    __shared__ float preB[65][65];   // [c][o], o=0..63 cols, o=64 scalar
    __shared__ float sufA[65][65];
    __shared__ float gsum[8][65];
    __shared__ float sAs[64], sAd[64];
    __shared__ int   Kv[256];

    const float* Wh   = (layer == 1) ? g_Wh : g_Wh2;
    float*       outp = (layer == 1) ? g_x  : g_z;
    const int istride = (layer == 1) ? 512 : 64;
    const int aStride = (layer == 1) ? 64 : 0;
    const int doElu   = (layer == 1) ? 1 : 0;

    int tid = threadIdx.x;
    int h = blockIdx.x, b = blockIdx.y;
    int rStart = blockIdx.z * rowsPerBlock;
    const float* base = Wh + (size_t)b * 512 * istride + h * 64;
    float* obase = outp + (size_t)b * 512 * istride + h * 64;

    if (tid < 64) { sAs[tid] = asrc[h * aStride + tid]; sAd[tid] = adst[h * aStride + tid]; }
    __syncthreads();

    int warp = tid >> 5, l = tid & 31;
    // s_src / d for ALL 512 rows (16 warps x 32 rows)
    for (int n = warp * 32; n < warp * 32 + 32; n++) {
        const float* row = base + (size_t)n * istride;
        float v0 = row[l], v1 = row[l + 32];
        float ps = v0 * sAs[l] + v1 * sAs[l + 32];
        float pd = v0 * sAd[l] + v1 * sAd[l + 32];
#pragma unroll
        for (int off = 16; off; off >>= 1) {
            ps += __shfl_xor_sync(0xffffffffu, ps, off);
            pd += __shfl_xor_sync(0xffffffffu, pd, off);
        }
        if (l == 0) { ssrc[n] = ps; dv[n] = pd; perm[n] = n; }
    }
    __syncthreads();

    // register-resident bitonic sort (shfl for j<32, smem exchange for j>=32)
    float key = dv[tid];
    int   pm  = perm[tid];
    for (int k = 2; k <= 512; k <<= 1) {
        for (int j = k >> 1; j > 0; j >>= 1) {
            float pk; int pp;
            if (j >= 32) {
                __syncthreads();
                dv[tid] = key; perm[tid] = pm;
                __syncthreads();
                pk = dv[tid ^ j]; pp = perm[tid ^ j];
            } else {
                pk = __shfl_xor_sync(0xffffffffu, key, j);
                pp = __shfl_xor_sync(0xffffffffu, pm, j);
            }
            bool up = ((tid & k) == 0);
            bool iLower = ((tid & j) == 0);
            bool wantMin = (up == iLower);
            bool take = wantMin ? (pk < key) : (pk > key);
            if (take) { key = pk; pm = pp; }
        }
    }
    __syncthreads();
    dv[tid] = key; perm[tid] = pm;
    __syncthreads();

    float dm = dv[511];
    {
        float d = key - dm;
        Ac[tid] = __expf(d);
        Bc[tid] = __expf(0.2f * d);
    }
    if (tid < 65) { preB[0][tid] = 0.f; sufA[64][tid] = 0.f; }
    __syncthreads();

    // chunk sums (64 chunks of 8, 65 "columns"; col 64 carries scalar sums)
    for (int it = tid; it < 64 * 65; it += 512) {
        int c = it / 65;
        int o = it - c * 65;
        float sA = 0.f, sB = 0.f;
#pragma unroll
        for (int q = 0; q < 8; q++) {
            int j = c * 8 + q;
            float v = (o < 64) ? base[(size_t)perm[j] * istride + o] : 1.0f;
            sA += Ac[j] * v;
            sB += Bc[j] * v;
        }
        sufA[c][o] = sA;
        preB[c + 1][o] = sB;
    }
    __syncthreads();

    // two-level prefix scan of preB over c = 1..64
    for (int it = tid; it < 8 * 65; it += 512) {
        int g = it / 65, o = it - g * 65;
        float run = 0.f;
#pragma unroll
        for (int k2 = 0; k2 < 8; k2++) {
            int c = g * 8 + 1 + k2;
            run += preB[c][o];
            preB[c][o] = run;
        }
        gsum[g][o] = run;
    }
    __syncthreads();
    if (tid < 65) {
        int o = tid;
        float run = 0.f;
#pragma unroll
        for (int g = 0; g < 8; g++) { float t = gsum[g][o]; gsum[g][o] = run; run += t; }
    }
    __syncthreads();
    for (int it = tid; it < 8 * 65; it += 512) {
        int g = it / 65, o = it - g * 65;
        float add = gsum[g][o];
#pragma unroll
        for (int k2 = 0; k2 < 8; k2++) preB[g * 8 + 1 + k2][o] += add;
    }
    __syncthreads();

    // two-level suffix scan of sufA over c = 63..0
    for (int it = tid; it < 8 * 65; it += 512) {
        int g = it / 65, o = it - g * 65;
        float run = 0.f;
#pragma unroll
        for (int k2 = 7; k2 >= 0; k2--) {
            int c = g * 8 + k2;
            run += sufA[c][o];
            sufA[c][o] = run;
        }
        gsum[g][o] = run;
    }
    __syncthreads();
    if (tid < 65) {
        int o = tid;
        float run = 0.f;
#pragma unroll
        for (int g = 7; g >= 0; g--) { float t = gsum[g][o]; gsum[g][o] = run; run += t; }
    }
    __syncthreads();
    for (int it = tid; it < 8 * 65; it += 512) {
        int g = it / 65, o = it - g * 65;
        float add = gsum[g][o];
#pragma unroll
        for (int k2 = 0; k2 < 8; k2++) sufA[g * 8 + k2][o] += add;
    }
    __syncthreads();

    // parallel binary searches for this block's row slice
    if (tid < rowsPerBlock) {
        float negs = -ssrc[rStart + tid];
        int lo = 0, hi = 512;
        while (lo < hi) { int mid = (lo + hi) >> 1; if (dv[mid] <= negs) lo = mid + 1; else hi = mid; }
        Kv[tid] = lo;
    }
    __syncthreads();

    // row outputs: warp per row, strided
    for (int ni = warp; ni < rowsPerBlock; ni += 16) {
        int n = rStart + ni;
        int K = Kv[ni];
        int cc = K >> 3;
        int ccp = (cc < 64) ? cc + 1 : 64;
        float t = ssrc[n] + dm;
        float m = fmaxf(t, 0.2f * t);
        float c1 = __expf(t - m), c2 = __expf(0.2f * t - m);

        float p0 = preB[cc][l],  p1 = preB[cc][l + 32],  pS = preB[cc][64];
        float s0 = sufA[ccp][l], s1 = sufA[ccp][l + 32], sS = sufA[ccp][64];
#pragma unroll
        for (int q = 0; q < 8; q++) {
            int j = cc * 8 + q;
            if (j < 512) {
                const float* prow = base + (size_t)perm[j] * istride;
                float v0 = prow[l], v1 = prow[l + 32];
                if (j < K) {
                    float wgt = Bc[j];
                    p0 += wgt * v0; p1 += wgt * v1; pS += wgt;
                } else {
                    float wgt = Ac[j];
                    s0 += wgt * v0; s1 += wgt * v1; sS += wgt;
                }
            }
        }
        float inv = 1.f / (c1 * sS + c2 * pS);
        float r0 = (c1 * s0 + c2 * p0) * inv;
        float r1 = (c1 * s1 + c2 * p1) * inv;
        if (doElu) {
            r0 = (r0 > 0.f) ? r0 : (__expf(r0) - 1.f);
            r1 = (r1 > 0.f) ? r1 : (__expf(r1) - 1.f);
        }
        obase[(size_t)n * istride + l] = r0;
        obase[(size_t)n * istride + l + 32] = r1;
    }
}

// ===================== fc1: z(32x32768) @ fc1_w(32768x256), split-K x64 =====================
__global__ __launch_bounds__(256) void fc1_partial_kernel(const float* __restrict__ w) {
    __shared__ float zs[32][136];
    int tid = threadIdx.x;
    int c0 = blockIdx.x * 64;
    int k0 = blockIdx.y * 512;
    int c = tid & 63, rq = tid >> 6;
    float acc[8];
#pragma unroll
    for (int i = 0; i < 8; i++) acc[i] = 0.f;

    for (int sub = 0; sub < 4; sub++) {
        int kb = k0 + sub * 128;
#pragma unroll
        for (int r = 0; r < 4; r++) {
            int idx = tid + r * 256;             // 1024 float4 slots = 32x128
            int row = idx >> 5;
            int kk = (idx & 31) * 4;
            *(float4*)&zs[row][kk] = *(const float4*)(g_z + (size_t)row * 32768 + kb + kk);
        }
        __syncthreads();
        for (int kk = 0; kk < 128; kk += 4) {
            float w0 = w[(size_t)(kb + kk + 0) * 256 + c0 + c];
            float w1 = w[(size_t)(kb + kk + 1) * 256 + c0 + c];
            float w2 = w[(size_t)(kb + kk + 2) * 256 + c0 + c];
            float w3 = w[(size_t)(kb + kk + 3) * 256 + c0 + c];
#pragma unroll
            for (int r8 = 0; r8 < 8; r8++) {
                float4 zv = *(float4*)&zs[rq * 8 + r8][kk];
                acc[r8] += zv.x * w0 + zv.y * w1 + zv.z * w2 + zv.w * w3;
            }
        }
        __syncthreads();
    }
#pragma unroll
    for (int r8 = 0; r8 < 8; r8++)
        g_part[(size_t)blockIdx.y * 8192 + (rq * 8 + r8) * 256 + c0 + c] = acc[r8];
}

__global__ void fc1_reduce_kernel(const float* __restrict__ bias) {
    int idx = blockIdx.x * 256 + threadIdx.x;   // 0..8191
    float s = bias[idx & 255];
    for (int q = 0; q < 64; q++) s += g_part[q * 8192 + idx];
    g_z1[idx] = fmaxf(s, 0.f);
}

__global__ __launch_bounds__(256) void fc2_kernel(const float* __restrict__ w,
                                                  const float* __restrict__ bias) {
    __shared__ float zs[32 * 260];
    int tid = threadIdx.x;
    for (int i = tid; i < 8192; i += 256) zs[(i >> 8) * 260 + (i & 255)] = g_z1[i];
    __syncthreads();
    int c = blockIdx.x * 8 + (tid & 7);
    int r = tid >> 3;
    float acc = bias[c];
#pragma unroll 8
    for (int k = 0; k < 256; k++) acc += zs[r * 260 + k] * w[k * 256 + c];
    g_z2[r * 256 + c] = fmaxf(acc, 0.f);
}

__global__ void fc3_kernel(const float* __restrict__ w, const float* __restrict__ bias,
                           float* __restrict__ outp) {
    int tid = threadIdx.x;       // 128 threads = 32 rows x 4 actions
    int r = tid >> 2, a = tid & 3;
    float acc = bias[a];
#pragma unroll 8
    for (int k = 0; k < 256; k++) acc += g_z2[r * 256 + k] * w[k * 4 + a];
    outp[r * 4 + a] = tanhf(acc);   // MAX_ACTION = 1.0
}

// ===================== launch =====================
extern "C" void kernel_launch(void* const* d_in, const int* in_sizes, int n_in,
                              void* d_out, int out_size) {
    const float* state     = (const float*)d_in[0];
    const float* W_heads   = (const float*)d_in[1];
    const float* a_src     = (const float*)d_in[2];
    const float* a_dst     = (const float*)d_in[3];
    const float* W_out     = (const float*)d_in[4];
    const float* a_out_src = (const float*)d_in[5];
    const float* a_out_dst = (const float*)d_in[6];
    const float* fc1_w     = (const float*)d_in[7];
    const float* fc1_b     = (const float*)d_in[8];
    const float* fc2_w     = (const float*)d_in[9];
    const float* fc2_b     = (const float*)d_in[10];
    const float* fc3_w     = (const float*)d_in[11];
    const float* fc3_b     = (const float*)d_in[12];
    float* out = (float*)d_out;

    gemm1_mma<<<dim3(4, 128), 256>>>(state, W_heads);
    attend_kernel<<<dim3(8, 32, 2), 512>>>(1, 256, a_src, a_dst);         // 512 blocks
    gemm2_mma<<<128, 256>>>(W_out);
    attend_kernel<<<dim3(1, 32, 4), 512>>>(2, 128, a_out_src, a_out_dst); // 128 blocks
    fc1_partial_kernel<<<dim3(4, 64), 256>>>(fc1_w);
    fc1_reduce_kernel<<<32, 256>>>(fc1_b);
    fc2_kernel<<<32, 256>>>(fc2_w, fc2_b);
    fc3_kernel<<<1, 128>>>(fc3_w, fc3_b, out);
}

// round 6
// speedup vs baseline: 2.6003x; 1.1198x over previous
#include <cuda_runtime.h>
#include <cuda_bf16.h>
#include <cstdint>
#include <cstddef>

#define B_ 32
#define N_ 512
#define H_ 8
#define RTOT (B_ * N_)   // 16384

// ----------------- static device scratch (no allocation) -----------------
__device__ float g_Wh [(size_t)RTOT * 512];   // layer1 Wh   [r][h*64+o]
__device__ float g_x  [(size_t)RTOT * 512];   // layer1 out  [r][h*64+o]
__device__ float g_Wh2[(size_t)RTOT * 64];    // layer2 Wh2  [r][o]
__device__ float g_z  [(size_t)RTOT * 64];    // layer2 out  [r][o]  (== z 32x32768)
__device__ float g_part[64 * 32 * 256];       // fc1 split-K partials
__device__ float g_z1 [32 * 256];
__device__ float g_z2 [32 * 256];

// ----------------- mma helpers -----------------
__device__ __forceinline__ void mma_bf16(float* c, uint32_t a0, uint32_t a1,
                                         uint32_t a2, uint32_t a3,
                                         uint32_t b0, uint32_t b1) {
    asm volatile(
        "mma.sync.aligned.m16n8k16.row.col.f32.bf16.bf16.f32 "
        "{%0,%1,%2,%3}, {%4,%5,%6,%7}, {%8,%9}, {%0,%1,%2,%3};\n"
        : "+f"(c[0]), "+f"(c[1]), "+f"(c[2]), "+f"(c[3])
        : "r"(a0), "r"(a1), "r"(a2), "r"(a3), "r"(b0), "r"(b1));
}

__device__ __forceinline__ void split_bf16(float x, __nv_bfloat16& h, __nv_bfloat16& l) {
    h = __float2bfloat16(x);
    l = __float2bfloat16(x - __bfloat162float(h));
}

// ===================== GEMM1 (mma): state(16384x64) @ Wheads(64x512) -> g_Wh =====================
__global__ __launch_bounds__(256) void gemm1_mma(const float* __restrict__ A,
                                                 const float* __restrict__ W) {
    __shared__ __align__(16) __nv_bfloat16 Ah[128][40], Al[128][40];
    __shared__ __align__(16) __nv_bfloat16 Bh[128][40], Bl[128][40];
    int tid = threadIdx.x;
    int c0 = blockIdx.x * 128;
    int m0 = blockIdx.y * 128;
    int w = tid >> 5, lane = tid & 31;
    int g = lane >> 2, tig = lane & 3;
    int wm = w & 3, wn = w >> 2;          // warp tile: rows wm*32, cols wn*64

    float acc[2][8][4];
#pragma unroll
    for (int a = 0; a < 2; a++)
#pragma unroll
        for (int b = 0; b < 8; b++)
#pragma unroll
            for (int c = 0; c < 4; c++) acc[a][b][c] = 0.f;

    for (int kc = 0; kc < 64; kc += 32) {
        if (kc) __syncthreads();
        // A chunk 128x32 fp32 -> split bf16
#pragma unroll
        for (int r = 0; r < 4; r++) {
            int idx = tid + r * 256;
            int m = idx >> 3, kg = (idx & 7) * 4;
            float4 v = *(const float4*)(A + (size_t)(m0 + m) * 64 + kc + kg);
            split_bf16(v.x, Ah[m][kg + 0], Al[m][kg + 0]);
            split_bf16(v.y, Ah[m][kg + 1], Al[m][kg + 1]);
            split_bf16(v.z, Ah[m][kg + 2], Al[m][kg + 2]);
            split_bf16(v.w, Ah[m][kg + 3], Al[m][kg + 3]);
        }
        // B chunk 32x128 -> transposed split bf16 (Bs[n][k])
#pragma unroll
        for (int r = 0; r < 4; r++) {
            int idx = tid + r * 256;
            int k = idx >> 5, c4 = (idx & 31) * 4;
            int col = c0 + c4;
            int h = col >> 6, o = col & 63;
            float4 v = *(const float4*)(W + h * 4096 + (kc + k) * 64 + o);
            split_bf16(v.x, Bh[c4 + 0][k], Bl[c4 + 0][k]);
            split_bf16(v.y, Bh[c4 + 1][k], Bl[c4 + 1][k]);
            split_bf16(v.z, Bh[c4 + 2][k], Bl[c4 + 2][k]);
            split_bf16(v.w, Bh[c4 + 3][k], Bl[c4 + 3][k]);
        }
        __syncthreads();

#pragma unroll
        for (int ks = 0; ks < 32; ks += 16) {
            uint32_t ah[2][4], al[2][4];
            int cA = ks + 2 * tig;
#pragma unroll
            for (int tm = 0; tm < 2; tm++) {
                int r0 = wm * 32 + tm * 16 + g;
                ah[tm][0] = *(uint32_t*)&Ah[r0][cA];
                ah[tm][1] = *(uint32_t*)&Ah[r0 + 8][cA];
                ah[tm][2] = *(uint32_t*)&Ah[r0][cA + 8];
                ah[tm][3] = *(uint32_t*)&Ah[r0 + 8][cA + 8];
                al[tm][0] = *(uint32_t*)&Al[r0][cA];
                al[tm][1] = *(uint32_t*)&Al[r0 + 8][cA];
                al[tm][2] = *(uint32_t*)&Al[r0][cA + 8];
                al[tm][3] = *(uint32_t*)&Al[r0 + 8][cA + 8];
            }
#pragma unroll
            for (int tn = 0; tn < 8; tn++) {
                int n = wn * 64 + tn * 8 + g;
                uint32_t bh0 = *(uint32_t*)&Bh[n][cA], bh1 = *(uint32_t*)&Bh[n][cA + 8];
                uint32_t bl0 = *(uint32_t*)&Bl[n][cA], bl1 = *(uint32_t*)&Bl[n][cA + 8];
#pragma unroll
                for (int tm = 0; tm < 2; tm++) {
                    mma_bf16(acc[tm][tn], ah[tm][0], ah[tm][1], ah[tm][2], ah[tm][3], bh0, bh1);
                    mma_bf16(acc[tm][tn], ah[tm][0], ah[tm][1], ah[tm][2], ah[tm][3], bl0, bl1);
                    mma_bf16(acc[tm][tn], al[tm][0], al[tm][1], al[tm][2], al[tm][3], bh0, bh1);
                }
            }
        }
    }
#pragma unroll
    for (int tm = 0; tm < 2; tm++)
#pragma unroll
        for (int tn = 0; tn < 8; tn++) {
            int r0 = m0 + wm * 32 + tm * 16 + g;
            int c = c0 + wn * 64 + tn * 8 + 2 * tig;
            float2 v0 = make_float2(acc[tm][tn][0], acc[tm][tn][1]);
            float2 v1 = make_float2(acc[tm][tn][2], acc[tm][tn][3]);
            *(float2*)&g_Wh[(size_t)r0 * 512 + c] = v0;
            *(float2*)&g_Wh[(size_t)(r0 + 8) * 512 + c] = v1;
        }
}

// ===================== GEMM2 (mma): g_x(16384x512) @ W_out(512x64) -> g_Wh2 =====================
__global__ __launch_bounds__(256) void gemm2_mma(const float* __restrict__ W) {
    __shared__ __align__(16) __nv_bfloat16 Ah[128][40], Al[128][40];
    __shared__ __align__(16) __nv_bfloat16 Bh[64][40], Bl[64][40];
    int tid = threadIdx.x;
    int m0 = blockIdx.x * 128;
    int w = tid >> 5, lane = tid & 31;
    int g = lane >> 2, tig = lane & 3;

    float acc[8][4];
#pragma unroll
    for (int b = 0; b < 8; b++)
#pragma unroll
        for (int c = 0; c < 4; c++) acc[b][c] = 0.f;

    for (int kc = 0; kc < 512; kc += 32) {
        if (kc) __syncthreads();
#pragma unroll
        for (int r = 0; r < 4; r++) {
            int idx = tid + r * 256;
            int m = idx >> 3, kg = (idx & 7) * 4;
            float4 v = *(const float4*)(g_x + (size_t)(m0 + m) * 512 + kc + kg);
            split_bf16(v.x, Ah[m][kg + 0], Al[m][kg + 0]);
            split_bf16(v.y, Ah[m][kg + 1], Al[m][kg + 1]);
            split_bf16(v.z, Ah[m][kg + 2], Al[m][kg + 2]);
            split_bf16(v.w, Ah[m][kg + 3], Al[m][kg + 3]);
        }
#pragma unroll
        for (int r = 0; r < 2; r++) {
            int idx = tid + r * 256;
            int k = idx >> 4, o4 = (idx & 15) * 4;
            float4 v = *(const float4*)(W + (size_t)(kc + k) * 64 + o4);
            split_bf16(v.x, Bh[o4 + 0][k], Bl[o4 + 0][k]);
            split_bf16(v.y, Bh[o4 + 1][k], Bl[o4 + 1][k]);
            split_bf16(v.z, Bh[o4 + 2][k], Bl[o4 + 2][k]);
            split_bf16(v.w, Bh[o4 + 3][k], Bl[o4 + 3][k]);
        }
        __syncthreads();

#pragma unroll
        for (int ks = 0; ks < 32; ks += 16) {
            int cA = ks + 2 * tig;
            int r0 = w * 16 + g;
            uint32_t ah0 = *(uint32_t*)&Ah[r0][cA],     ah1 = *(uint32_t*)&Ah[r0 + 8][cA];
            uint32_t ah2 = *(uint32_t*)&Ah[r0][cA + 8], ah3 = *(uint32_t*)&Ah[r0 + 8][cA + 8];
            uint32_t al0 = *(uint32_t*)&Al[r0][cA],     al1 = *(uint32_t*)&Al[r0 + 8][cA];
            uint32_t al2 = *(uint32_t*)&Al[r0][cA + 8], al3 = *(uint32_t*)&Al[r0 + 8][cA + 8];
#pragma unroll
            for (int tn = 0; tn < 8; tn++) {
                int n = tn * 8 + g;
                uint32_t bh0 = *(uint32_t*)&Bh[n][cA], bh1 = *(uint32_t*)&Bh[n][cA + 8];
                uint32_t bl0 = *(uint32_t*)&Bl[n][cA], bl1 = *(uint32_t*)&Bl[n][cA + 8];
                mma_bf16(acc[tn], ah0, ah1, ah2, ah3, bh0, bh1);
                mma_bf16(acc[tn], ah0, ah1, ah2, ah3, bl0, bl1);
                mma_bf16(acc[tn], al0, al1, al2, al3, bh0, bh1);
            }
        }
    }
#pragma unroll
    for (int tn = 0; tn < 8; tn++) {
        int r0 = m0 + w * 16 + g;
        int c = tn * 8 + 2 * tig;
        *(float2*)&g_Wh2[(size_t)r0 * 64 + c] = make_float2(acc[tn][0], acc[tn][1]);
        *(float2*)&g_Wh2[(size_t)(r0 + 8) * 64 + c] = make_float2(acc[tn][2], acc[tn][3]);
    }
}

// ===================== factorized GAT attention (1024 threads, row-split) =====================
// e[i,j] = leaky_relu(s_i + d_j): positive set is a suffix in d-sorted order.
__global__ __launch_bounds__(1024) void attend_kernel(int layer, int rowsPerBlock,
                                                      const float* __restrict__ asrc,
                                                      const float* __restrict__ adst) {
    __shared__ float dv[512];
    __shared__ int   perm[512];
    __shared__ float ssrc[512];
    __shared__ float Ac[512];
    __shared__ float Bc[512];
    __shared__ float preB[65][65];   // [c][o], o=0..63 cols, o=64 scalar
    __shared__ float sufA[65][65];
    __shared__ float gsum[8][65];
    __shared__ float sAs[64], sAd[64];
    __shared__ int   Kv[512];

    const float* Wh   = (layer == 1) ? g_Wh : g_Wh2;
    float*       outp = (layer == 1) ? g_x  : g_z;
    const int istride = (layer == 1) ? 512 : 64;
    const int aStride = (layer == 1) ? 64 : 0;
    const int doElu   = (layer == 1) ? 1 : 0;

    int tid = threadIdx.x;
    int h = blockIdx.x, b = blockIdx.y;
    int rStart = blockIdx.z * rowsPerBlock;
    const float* base = Wh + (size_t)b * 512 * istride + h * 64;
    float* obase = outp + (size_t)b * 512 * istride + h * 64;

    if (tid < 64) { sAs[tid] = asrc[h * aStride + tid]; sAd[tid] = adst[h * aStride + tid]; }
    __syncthreads();

    int warp = tid >> 5, l = tid & 31;
    // s_src / d for ALL 512 rows (32 warps x 16 rows)
    for (int n = warp * 16; n < warp * 16 + 16; n++) {
        const float* row = base + (size_t)n * istride;
        float v0 = row[l], v1 = row[l + 32];
        float ps = v0 * sAs[l] + v1 * sAs[l + 32];
        float pd = v0 * sAd[l] + v1 * sAd[l + 32];
#pragma unroll
        for (int off = 16; off; off >>= 1) {
            ps += __shfl_xor_sync(0xffffffffu, ps, off);
            pd += __shfl_xor_sync(0xffffffffu, pd, off);
        }
        if (l == 0) { ssrc[n] = ps; dv[n] = pd; perm[n] = n; }
    }
    __syncthreads();

    // register-resident bitonic sort on tid<512 (shfl j<32, smem exchange j>=32)
    float key = (tid < 512) ? dv[tid] : 0.f;
    int   pm  = (tid < 512) ? perm[tid] : 0;
    for (int k = 2; k <= 512; k <<= 1) {
        for (int j = k >> 1; j > 0; j >>= 1) {
            if (j >= 32) {
                __syncthreads();
                if (tid < 512) { dv[tid] = key; perm[tid] = pm; }
                __syncthreads();
                if (tid < 512) {
                    float pk = dv[tid ^ j]; int pp = perm[tid ^ j];
                    bool up = ((tid & k) == 0);
                    bool iLower = ((tid & j) == 0);
                    bool wantMin = (up == iLower);
                    if (wantMin ? (pk < key) : (pk > key)) { key = pk; pm = pp; }
                }
            } else if (tid < 512) {
                float pk = __shfl_xor_sync(0xffffffffu, key, j);
                int   pp = __shfl_xor_sync(0xffffffffu, pm, j);
                bool up = ((tid & k) == 0);
                bool iLower = ((tid & j) == 0);
                bool wantMin = (up == iLower);
                if (wantMin ? (pk < key) : (pk > key)) { key = pk; pm = pp; }
            }
        }
    }
    __syncthreads();
    if (tid < 512) { dv[tid] = key; perm[tid] = pm; }
    __syncthreads();

    float dm = dv[511];
    if (tid < 512) {
        float d = key - dm;
        Ac[tid] = __expf(d);
        Bc[tid] = __expf(0.2f * d);
    }
    if (tid < 65) { preB[0][tid] = 0.f; sufA[64][tid] = 0.f; }
    __syncthreads();

    // chunk sums (64 chunks of 8, 65 "columns"; col 64 carries scalar sums)
    for (int it = tid; it < 64 * 65; it += 1024) {
        int c = it / 65;
        int o = it - c * 65;
        float sA = 0.f, sB = 0.f;
#pragma unroll
        for (int q = 0; q < 8; q++) {
            int j = c * 8 + q;
            float v = (o < 64) ? base[(size_t)perm[j] * istride + o] : 1.0f;
            sA += Ac[j] * v;
            sB += Bc[j] * v;
        }
        sufA[c][o] = sA;
        preB[c + 1][o] = sB;
    }
    __syncthreads();

    // two-level prefix scan of preB over c = 1..64
    for (int it = tid; it < 8 * 65; it += 1024) {
        int g = it / 65, o = it - g * 65;
        float run = 0.f;
#pragma unroll
        for (int k2 = 0; k2 < 8; k2++) {
            int c = g * 8 + 1 + k2;
            run += preB[c][o];
            preB[c][o] = run;
        }
        gsum[g][o] = run;
    }
    __syncthreads();
    if (tid < 65) {
        int o = tid;
        float run = 0.f;
#pragma unroll
        for (int g = 0; g < 8; g++) { float t = gsum[g][o]; gsum[g][o] = run; run += t; }
    }
    __syncthreads();
    for (int it = tid; it < 8 * 65; it += 1024) {
        int g = it / 65, o = it - g * 65;
        float add = gsum[g][o];
#pragma unroll
        for (int k2 = 0; k2 < 8; k2++) preB[g * 8 + 1 + k2][o] += add;
    }
    __syncthreads();

    // two-level suffix scan of sufA over c = 63..0
    for (int it = tid; it < 8 * 65; it += 1024) {
        int g = it / 65, o = it - g * 65;
        float run = 0.f;
#pragma unroll
        for (int k2 = 7; k2 >= 0; k2--) {
            int c = g * 8 + k2;
            run += sufA[c][o];
            sufA[c][o] = run;
        }
        gsum[g][o] = run;
    }
    __syncthreads();
    if (tid < 65) {
        int o = tid;
        float run = 0.f;
#pragma unroll
        for (int g = 7; g >= 0; g--) { float t = gsum[g][o]; gsum[g][o] = run; run += t; }
    }
    __syncthreads();
    for (int it = tid; it < 8 * 65; it += 1024) {
        int g = it / 65, o = it - g * 65;
        float add = gsum[g][o];
#pragma unroll
        for (int k2 = 0; k2 < 8; k2++) sufA[g * 8 + k2][o] += add;
    }
    __syncthreads();

    // parallel binary searches for this block's row slice
    if (tid < rowsPerBlock) {
        float negs = -ssrc[rStart + tid];
        int lo = 0, hi = 512;
        while (lo < hi) { int mid = (lo + hi) >> 1; if (dv[mid] <= negs) lo = mid + 1; else hi = mid; }
        Kv[tid] = lo;
    }
    __syncthreads();

    // row outputs: warp per row, strided over 32 warps
    for (int ni = warp; ni < rowsPerBlock; ni += 32) {
        int n = rStart + ni;
        int K = Kv[ni];
        int cc = K >> 3;
        int ccp = (cc < 64) ? cc + 1 : 64;
        float t = ssrc[n] + dm;
        float m = fmaxf(t, 0.2f * t);
        float c1 = __expf(t - m), c2 = __expf(0.2f * t - m);

        float p0 = preB[cc][l],  p1 = preB[cc][l + 32],  pS = preB[cc][64];
        float s0 = sufA[ccp][l], s1 = sufA[ccp][l + 32], sS = sufA[ccp][64];
#pragma unroll
        for (int q = 0; q < 8; q++) {
            int j = cc * 8 + q;
            if (j < 512) {
                const float* prow = base + (size_t)perm[j] * istride;
                float v0 = prow[l], v1 = prow[l + 32];
                if (j < K) {
                    float wgt = Bc[j];
                    p0 += wgt * v0; p1 += wgt * v1; pS += wgt;
                } else {
                    float wgt = Ac[j];
                    s0 += wgt * v0; s1 += wgt * v1; sS += wgt;
                }
            }
        }
        float inv = 1.f / (c1 * sS + c2 * pS);
        float r0 = (c1 * s0 + c2 * p0) * inv;
        float r1 = (c1 * s1 + c2 * p1) * inv;
        if (doElu) {
            r0 = (r0 > 0.f) ? r0 : (__expf(r0) - 1.f);
            r1 = (r1 > 0.f) ? r1 : (__expf(r1) - 1.f);
        }
        obase[(size_t)n * istride + l] = r0;
        obase[(size_t)n * istride + l + 32] = r1;
    }
}

// ===================== fc1: z(32x32768) @ fc1_w(32768x256), split-K x64 =====================
__global__ __launch_bounds__(256) void fc1_partial_kernel(const float* __restrict__ w) {
    __shared__ float zs[32][136];
    int tid = threadIdx.x;
    int c0 = blockIdx.x * 64;
    int k0 = blockIdx.y * 512;
    int c = tid & 63, rq = tid >> 6;
    float acc[8];
#pragma unroll
    for (int i = 0; i < 8; i++) acc[i] = 0.f;

    for (int sub = 0; sub < 4; sub++) {
        int kb = k0 + sub * 128;
#pragma unroll
        for (int r = 0; r < 4; r++) {
            int idx = tid + r * 256;             // 1024 float4 slots = 32x128
            int row = idx >> 5;
            int kk = (idx & 31) * 4;
            *(float4*)&zs[row][kk] = *(const float4*)(g_z + (size_t)row * 32768 + kb + kk);
        }
        __syncthreads();
        for (int kk = 0; kk < 128; kk += 4) {
            float w0 = w[(size_t)(kb + kk + 0) * 256 + c0 + c];
            float w1 = w[(size_t)(kb + kk + 1) * 256 + c0 + c];
            float w2 = w[(size_t)(kb + kk + 2) * 256 + c0 + c];
            float w3 = w[(size_t)(kb + kk + 3) * 256 + c0 + c];
#pragma unroll
            for (int r8 = 0; r8 < 8; r8++) {
                float4 zv = *(float4*)&zs[rq * 8 + r8][kk];
                acc[r8] += zv.x * w0 + zv.y * w1 + zv.z * w2 + zv.w * w3;
            }
        }
        __syncthreads();
    }
#pragma unroll
    for (int r8 = 0; r8 < 8; r8++)
        g_part[(size_t)blockIdx.y * 8192 + (rq * 8 + r8) * 256 + c0 + c] = acc[r8];
}

__global__ void fc1_reduce_kernel(const float* __restrict__ bias) {
    int idx = blockIdx.x * 256 + threadIdx.x;   // 0..8191
    float s = bias[idx & 255];
    for (int q = 0; q < 64; q++) s += g_part[q * 8192 + idx];
    g_z1[idx] = fmaxf(s, 0.f);
}

__global__ __launch_bounds__(256) void fc2_kernel(const float* __restrict__ w,
                                                  const float* __restrict__ bias) {
    __shared__ float zs[32 * 260];
    int tid = threadIdx.x;
    for (int i = tid; i < 8192; i += 256) zs[(i >> 8) * 260 + (i & 255)] = g_z1[i];
    __syncthreads();
    int c = blockIdx.x * 8 + (tid & 7);
    int r = tid >> 3;
    float acc = bias[c];
#pragma unroll 8
    for (int k = 0; k < 256; k++) acc += zs[r * 260 + k] * w[k * 256 + c];
    g_z2[r * 256 + c] = fmaxf(acc, 0.f);
}

__global__ void fc3_kernel(const float* __restrict__ w, const float* __restrict__ bias,
                           float* __restrict__ outp) {
    int tid = threadIdx.x;       // 256 threads = 128 (r,a) pairs x 2-way k split
    int p = tid >> 1, half = tid & 1;
    int r = p >> 2, a = p & 3;
    float acc = 0.f;
    int kb = half * 128;
#pragma unroll 8
    for (int k = 0; k < 128; k++) acc += g_z2[r * 256 + kb + k] * w[(kb + k) * 4 + a];
    acc += __shfl_xor_sync(0xffffffffu, acc, 1);
    if (half == 0) outp[r * 4 + a] = tanhf(acc + bias[a]);   // MAX_ACTION = 1.0
}

// ===================== launch =====================
extern "C" void kernel_launch(void* const* d_in, const int* in_sizes, int n_in,
                              void* d_out, int out_size) {
    const float* state     = (const float*)d_in[0];
    const float* W_heads   = (const float*)d_in[1];
    const float* a_src     = (const float*)d_in[2];
    const float* a_dst     = (const float*)d_in[3];
    const float* W_out     = (const float*)d_in[4];
    const float* a_out_src = (const float*)d_in[5];
    const float* a_out_dst = (const float*)d_in[6];
    const float* fc1_w     = (const float*)d_in[7];
    const float* fc1_b     = (const float*)d_in[8];
    const float* fc2_w     = (const float*)d_in[9];
    const float* fc2_b     = (const float*)d_in[10];
    const float* fc3_w     = (const float*)d_in[11];
    const float* fc3_b     = (const float*)d_in[12];
    float* out = (float*)d_out;

    gemm1_mma<<<dim3(4, 128), 256>>>(state, W_heads);
    attend_kernel<<<dim3(8, 32, 1), 1024>>>(1, 512, a_src, a_dst);         // 256 blocks
    gemm2_mma<<<128, 256>>>(W_out);
    attend_kernel<<<dim3(1, 32, 4), 1024>>>(2, 128, a_out_src, a_out_dst); // 128 blocks
    fc1_partial_kernel<<<dim3(4, 64), 256>>>(fc1_w);
    fc1_reduce_kernel<<<32, 256>>>(fc1_b);
    fc2_kernel<<<32, 256>>>(fc2_w, fc2_b);
    fc3_kernel<<<1, 256>>>(fc3_w, fc3_b, out);
}

// round 7
// speedup vs baseline: 2.8502x; 1.0961x over previous
#include <cuda_runtime.h>
#include <cuda_bf16.h>
#include <cstdint>
#include <cstddef>

#define B_ 32
#define N_ 512
#define H_ 8
#define RTOT (B_ * N_)   // 16384

// ----------------- static device scratch (no allocation) -----------------
__device__ float g_Wh [(size_t)RTOT * 512];            // layer1 Wh fp32
__device__ __nv_bfloat16 g_xh[(size_t)RTOT * 512];     // layer1 out split
__device__ __nv_bfloat16 g_xl[(size_t)RTOT * 512];
__device__ float g_Wh2[(size_t)RTOT * 64];             // layer2 Wh2 fp32
__device__ __nv_bfloat16 g_zh[(size_t)RTOT * 64];      // layer2 out split (z 32x32768)
__device__ __nv_bfloat16 g_zl[(size_t)RTOT * 64];
__device__ __nv_bfloat16 g_sth[1048576], g_stl[1048576];   // state split
__device__ __nv_bfloat16 g_whh[32768],  g_whl[32768];      // W_heads split
__device__ __nv_bfloat16 g_woh[32768],  g_wol[32768];      // W_out split
__device__ float g_part[128 * 8192];                   // fc1 split-K partials
__device__ float g_z1[8192];
__device__ float g_z2[8192];

// ----------------- helpers -----------------
__device__ __forceinline__ void mma_bf16(float* c, uint32_t a0, uint32_t a1,
                                         uint32_t a2, uint32_t a3,
                                         uint32_t b0, uint32_t b1) {
    asm volatile(
        "mma.sync.aligned.m16n8k16.row.col.f32.bf16.bf16.f32 "
        "{%0,%1,%2,%3}, {%4,%5,%6,%7}, {%8,%9}, {%0,%1,%2,%3};\n"
        : "+f"(c[0]), "+f"(c[1]), "+f"(c[2]), "+f"(c[3])
        : "r"(a0), "r"(a1), "r"(a2), "r"(a3), "r"(b0), "r"(b1));
}

__device__ __forceinline__ void split_bf16(float x, __nv_bfloat16& h, __nv_bfloat16& l) {
    h = __float2bfloat16(x);
    l = __float2bfloat16(x - __bfloat162float(h));
}

// ===================== prep: split fp32 inputs into bf16 h/l =====================
__global__ void prep_split(const float* __restrict__ st, const float* __restrict__ wh,
                           const float* __restrict__ wo) {
    int i = blockIdx.x * 256 + threadIdx.x;
    if (i < 1048576) {
        __nv_bfloat16 h, l; split_bf16(st[i], h, l);
        g_sth[i] = h; g_stl[i] = l;
    } else if (i < 1048576 + 32768) {
        int j = i - 1048576;
        __nv_bfloat16 h, l; split_bf16(wh[j], h, l);
        g_whh[j] = h; g_whl[j] = l;
    } else {
        int j = i - 1048576 - 32768;
        __nv_bfloat16 h, l; split_bf16(wo[j], h, l);
        g_woh[j] = h; g_wol[j] = l;
    }
}

// ===================== GEMM1 (mma): state(16384x64) @ Wheads(64x512) -> g_Wh =====================
__global__ __launch_bounds__(256) void gemm1_mma() {
    __shared__ __align__(16) __nv_bfloat16 Ah[128][40], Al[128][40];
    __shared__ __align__(16) __nv_bfloat16 Bh[128][40], Bl[128][40];
    int tid = threadIdx.x;
    int c0 = blockIdx.x * 128;
    int m0 = blockIdx.y * 128;
    int w = tid >> 5, lane = tid & 31;
    int g = lane >> 2, tig = lane & 3;
    int wm = w & 3, wn = w >> 2;

    float acc[2][8][4];
#pragma unroll
    for (int a = 0; a < 2; a++)
#pragma unroll
        for (int b = 0; b < 8; b++)
#pragma unroll
            for (int c = 0; c < 4; c++) acc[a][b][c] = 0.f;

    for (int kc = 0; kc < 64; kc += 32) {
        if (kc) __syncthreads();
        // A chunk 128x32 : raw bf16 copies
#pragma unroll
        for (int r = 0; r < 2; r++) {
            int idx = tid + r * 256;
            int m = idx >> 2, kg = (idx & 3) * 8;
            *(uint4*)&Ah[m][kg] = *(const uint4*)(g_sth + (size_t)(m0 + m) * 64 + kc + kg);
            *(uint4*)&Al[m][kg] = *(const uint4*)(g_stl + (size_t)(m0 + m) * 64 + kc + kg);
        }
        // B chunk 32x128 : transposed store Bs[n][k]
#pragma unroll
        for (int r = 0; r < 2; r++) {
            int idx = tid + r * 256;
            int k = idx >> 4, c8 = (idx & 15) * 8;
            int col = c0 + c8;
            int hh = col >> 6, o = col & 63;
            uint4 vh = *(const uint4*)(g_whh + hh * 4096 + (kc + k) * 64 + o);
            uint4 vl = *(const uint4*)(g_whl + hh * 4096 + (kc + k) * 64 + o);
            __nv_bfloat16 th[8], tl[8];
            *(uint4*)th = vh; *(uint4*)tl = vl;
#pragma unroll
            for (int i = 0; i < 8; i++) { Bh[c8 + i][k] = th[i]; Bl[c8 + i][k] = tl[i]; }
        }
        __syncthreads();

#pragma unroll
        for (int ks = 0; ks < 32; ks += 16) {
            uint32_t ah[2][4], al[2][4];
            int cA = ks + 2 * tig;
#pragma unroll
            for (int tm = 0; tm < 2; tm++) {
                int r0 = wm * 32 + tm * 16 + g;
                ah[tm][0] = *(uint32_t*)&Ah[r0][cA];
                ah[tm][1] = *(uint32_t*)&Ah[r0 + 8][cA];
                ah[tm][2] = *(uint32_t*)&Ah[r0][cA + 8];
                ah[tm][3] = *(uint32_t*)&Ah[r0 + 8][cA + 8];
                al[tm][0] = *(uint32_t*)&Al[r0][cA];
                al[tm][1] = *(uint32_t*)&Al[r0 + 8][cA];
                al[tm][2] = *(uint32_t*)&Al[r0][cA + 8];
                al[tm][3] = *(uint32_t*)&Al[r0 + 8][cA + 8];
            }
#pragma unroll
            for (int tn = 0; tn < 8; tn++) {
                int n = wn * 64 + tn * 8 + g;
                uint32_t bh0 = *(uint32_t*)&Bh[n][cA], bh1 = *(uint32_t*)&Bh[n][cA + 8];
                uint32_t bl0 = *(uint32_t*)&Bl[n][cA], bl1 = *(uint32_t*)&Bl[n][cA + 8];
#pragma unroll
                for (int tm = 0; tm < 2; tm++) {
                    mma_bf16(acc[tm][tn], ah[tm][0], ah[tm][1], ah[tm][2], ah[tm][3], bh0, bh1);
                    mma_bf16(acc[tm][tn], ah[tm][0], ah[tm][1], ah[tm][2], ah[tm][3], bl0, bl1);
                    mma_bf16(acc[tm][tn], al[tm][0], al[tm][1], al[tm][2], al[tm][3], bh0, bh1);
                }
            }
        }
    }
#pragma unroll
    for (int tm = 0; tm < 2; tm++)
#pragma unroll
        for (int tn = 0; tn < 8; tn++) {
            int r0 = m0 + wm * 32 + tm * 16 + g;
            int c = c0 + wn * 64 + tn * 8 + 2 * tig;
            *(float2*)&g_Wh[(size_t)r0 * 512 + c] = make_float2(acc[tm][tn][0], acc[tm][tn][1]);
            *(float2*)&g_Wh[(size_t)(r0 + 8) * 512 + c] = make_float2(acc[tm][tn][2], acc[tm][tn][3]);
        }
}

// ===================== GEMM2 (mma): g_x(16384x512) @ W_out(512x64) -> g_Wh2 =====================
__global__ __launch_bounds__(256) void gemm2_mma() {
    __shared__ __align__(16) __nv_bfloat16 Ah[128][40], Al[128][40];
    __shared__ __align__(16) __nv_bfloat16 Bh[64][40], Bl[64][40];
    int tid = threadIdx.x;
    int m0 = blockIdx.x * 128;
    int w = tid >> 5, lane = tid & 31;
    int g = lane >> 2, tig = lane & 3;

    float acc[8][4];
#pragma unroll
    for (int b = 0; b < 8; b++)
#pragma unroll
        for (int c = 0; c < 4; c++) acc[b][c] = 0.f;

    for (int kc = 0; kc < 512; kc += 32) {
        if (kc) __syncthreads();
#pragma unroll
        for (int r = 0; r < 2; r++) {
            int idx = tid + r * 256;
            int m = idx >> 2, kg = (idx & 3) * 8;
            *(uint4*)&Ah[m][kg] = *(const uint4*)(g_xh + (size_t)(m0 + m) * 512 + kc + kg);
            *(uint4*)&Al[m][kg] = *(const uint4*)(g_xl + (size_t)(m0 + m) * 512 + kc + kg);
        }
        {
            int k = tid >> 3, o8 = (tid & 7) * 8;
            uint4 vh = *(const uint4*)(g_woh + (kc + k) * 64 + o8);
            uint4 vl = *(const uint4*)(g_wol + (kc + k) * 64 + o8);
            __nv_bfloat16 th[8], tl[8];
            *(uint4*)th = vh; *(uint4*)tl = vl;
#pragma unroll
            for (int i = 0; i < 8; i++) { Bh[o8 + i][k] = th[i]; Bl[o8 + i][k] = tl[i]; }
        }
        __syncthreads();

#pragma unroll
        for (int ks = 0; ks < 32; ks += 16) {
            int cA = ks + 2 * tig;
            int r0 = w * 16 + g;
            uint32_t ah0 = *(uint32_t*)&Ah[r0][cA],     ah1 = *(uint32_t*)&Ah[r0 + 8][cA];
            uint32_t ah2 = *(uint32_t*)&Ah[r0][cA + 8], ah3 = *(uint32_t*)&Ah[r0 + 8][cA + 8];
            uint32_t al0 = *(uint32_t*)&Al[r0][cA],     al1 = *(uint32_t*)&Al[r0 + 8][cA];
            uint32_t al2 = *(uint32_t*)&Al[r0][cA + 8], al3 = *(uint32_t*)&Al[r0 + 8][cA + 8];
#pragma unroll
            for (int tn = 0; tn < 8; tn++) {
                int n = tn * 8 + g;
                uint32_t bh0 = *(uint32_t*)&Bh[n][cA], bh1 = *(uint32_t*)&Bh[n][cA + 8];
                uint32_t bl0 = *(uint32_t*)&Bl[n][cA], bl1 = *(uint32_t*)&Bl[n][cA + 8];
                mma_bf16(acc[tn], ah0, ah1, ah2, ah3, bh0, bh1);
                mma_bf16(acc[tn], ah0, ah1, ah2, ah3, bl0, bl1);
                mma_bf16(acc[tn], al0, al1, al2, al3, bh0, bh1);
            }
        }
    }
#pragma unroll
    for (int tn = 0; tn < 8; tn++) {
        int r0 = m0 + w * 16 + g;
        int c = tn * 8 + 2 * tig;
        *(float2*)&g_Wh2[(size_t)r0 * 64 + c] = make_float2(acc[tn][0], acc[tn][1]);
        *(float2*)&g_Wh2[(size_t)(r0 + 8) * 64 + c] = make_float2(acc[tn][2], acc[tn][3]);
    }
}

// ===================== factorized GAT attention (1024 threads, row-split) =====================
// e[i,j] = leaky_relu(s_i + d_j): positive set is a suffix in d-sorted order.
__global__ __launch_bounds__(1024) void attend_kernel(int layer, int rowsPerBlock,
                                                      const float* __restrict__ asrc,
                                                      const float* __restrict__ adst) {
    __shared__ float dv[512];
    __shared__ int   perm[512];
    __shared__ float ssrc[512];
    __shared__ float Ac[512];
    __shared__ float Bc[512];
    __shared__ float preB[65][65];   // [c][o], o=0..63 cols, o=64 scalar
    __shared__ float sufA[65][65];
    __shared__ float gsum[8][65];
    __shared__ float sAs[64], sAd[64];
    __shared__ int   Kv[512];

    const float* Wh = (layer == 1) ? g_Wh : g_Wh2;
    __nv_bfloat16* outh = (layer == 1) ? g_xh : g_zh;
    __nv_bfloat16* outl = (layer == 1) ? g_xl : g_zl;
    const int istride = (layer == 1) ? 512 : 64;
    const int aStride = (layer == 1) ? 64 : 0;
    const int doElu   = (layer == 1) ? 1 : 0;

    int tid = threadIdx.x;
    int h = blockIdx.x, b = blockIdx.y;
    int rStart = blockIdx.z * rowsPerBlock;
    const float* base = Wh + (size_t)b * 512 * istride + h * 64;
    size_t obase = (size_t)b * 512 * istride + h * 64;

    if (tid < 64) { sAs[tid] = asrc[h * aStride + tid]; sAd[tid] = adst[h * aStride + tid]; }
    __syncthreads();

    int warp = tid >> 5, l = tid & 31;
    // s_src / d for ALL 512 rows (32 warps x 16 rows)
    for (int n = warp * 16; n < warp * 16 + 16; n++) {
        const float* row = base + (size_t)n * istride;
        float v0 = row[l], v1 = row[l + 32];
        float ps = v0 * sAs[l] + v1 * sAs[l + 32];
        float pd = v0 * sAd[l] + v1 * sAd[l + 32];
#pragma unroll
        for (int off = 16; off; off >>= 1) {
            ps += __shfl_xor_sync(0xffffffffu, ps, off);
            pd += __shfl_xor_sync(0xffffffffu, pd, off);
        }
        if (l == 0) { ssrc[n] = ps; dv[n] = pd; perm[n] = n; }
    }
    __syncthreads();

    // register-resident bitonic sort on tid<512 (shfl j<32, smem exchange j>=32)
    float key = (tid < 512) ? dv[tid] : 0.f;
    int   pm  = (tid < 512) ? perm[tid] : 0;
    for (int k = 2; k <= 512; k <<= 1) {
        for (int j = k >> 1; j > 0; j >>= 1) {
            if (j >= 32) {
                __syncthreads();
                if (tid < 512) { dv[tid] = key; perm[tid] = pm; }
                __syncthreads();
                if (tid < 512) {
                    float pk = dv[tid ^ j]; int pp = perm[tid ^ j];
                    bool up = ((tid & k) == 0);
                    bool iLower = ((tid & j) == 0);
                    bool wantMin = (up == iLower);
                    if (wantMin ? (pk < key) : (pk > key)) { key = pk; pm = pp; }
                }
            } else if (tid < 512) {
                float pk = __shfl_xor_sync(0xffffffffu, key, j);
                int   pp = __shfl_xor_sync(0xffffffffu, pm, j);
                bool up = ((tid & k) == 0);
                bool iLower = ((tid & j) == 0);
                bool wantMin = (up == iLower);
                if (wantMin ? (pk < key) : (pk > key)) { key = pk; pm = pp; }
            }
        }
    }
    __syncthreads();
    if (tid < 512) { dv[tid] = key; perm[tid] = pm; }
    __syncthreads();

    float dm = dv[511];
    if (tid < 512) {
        float d = key - dm;
        Ac[tid] = __expf(d);
        Bc[tid] = __expf(0.2f * d);
    }
    if (tid < 65) { preB[0][tid] = 0.f; sufA[64][tid] = 0.f; }
    __syncthreads();

    // chunk sums (64 chunks of 8, 65 "columns"; col 64 carries scalar sums)
    for (int it = tid; it < 64 * 65; it += 1024) {
        int c = it / 65;
        int o = it - c * 65;
        float sA = 0.f, sB = 0.f;
#pragma unroll
        for (int q = 0; q < 8; q++) {
            int j = c * 8 + q;
            float v = (o < 64) ? base[(size_t)perm[j] * istride + o] : 1.0f;
            sA += Ac[j] * v;
            sB += Bc[j] * v;
        }
        sufA[c][o] = sA;
        preB[c + 1][o] = sB;
    }
    __syncthreads();

    // two-level prefix scan of preB over c = 1..64
    for (int it = tid; it < 8 * 65; it += 1024) {
        int g = it / 65, o = it - g * 65;
        float run = 0.f;
#pragma unroll
        for (int k2 = 0; k2 < 8; k2++) {
            int c = g * 8 + 1 + k2;
            run += preB[c][o];
            preB[c][o] = run;
        }
        gsum[g][o] = run;
    }
    __syncthreads();
    if (tid < 65) {
        int o = tid;
        float run = 0.f;
#pragma unroll
        for (int g = 0; g < 8; g++) { float t = gsum[g][o]; gsum[g][o] = run; run += t; }
    }
    __syncthreads();
    for (int it = tid; it < 8 * 65; it += 1024) {
        int g = it / 65, o = it - g * 65;
        float add = gsum[g][o];
#pragma unroll
        for (int k2 = 0; k2 < 8; k2++) preB[g * 8 + 1 + k2][o] += add;
    }
    __syncthreads();

    // two-level suffix scan of sufA over c = 63..0
    for (int it = tid; it < 8 * 65; it += 1024) {
        int g = it / 65, o = it - g * 65;
        float run = 0.f;
#pragma unroll
        for (int k2 = 7; k2 >= 0; k2--) {
            int c = g * 8 + k2;
            run += sufA[c][o];
            sufA[c][o] = run;
        }
        gsum[g][o] = run;
    }
    __syncthreads();
    if (tid < 65) {
        int o = tid;
        float run = 0.f;
#pragma unroll
        for (int g = 7; g >= 0; g--) { float t = gsum[g][o]; gsum[g][o] = run; run += t; }
    }
    __syncthreads();
    for (int it = tid; it < 8 * 65; it += 1024) {
        int g = it / 65, o = it - g * 65;
        float add = gsum[g][o];
#pragma unroll
        for (int k2 = 0; k2 < 8; k2++) sufA[g * 8 + k2][o] += add;
    }
    __syncthreads();

    // parallel binary searches for this block's row slice
    if (tid < rowsPerBlock) {
        float negs = -ssrc[rStart + tid];
        int lo = 0, hi = 512;
        while (lo < hi) { int mid = (lo + hi) >> 1; if (dv[mid] <= negs) lo = mid + 1; else hi = mid; }
        Kv[tid] = lo;
    }
    __syncthreads();

    // row outputs: warp per row, strided over 32 warps; emit bf16 h/l split
    for (int ni = warp; ni < rowsPerBlock; ni += 32) {
        int n = rStart + ni;
        int K = Kv[ni];
        int cc = K >> 3;
        int ccp = (cc < 64) ? cc + 1 : 64;
        float t = ssrc[n] + dm;
        float m = fmaxf(t, 0.2f * t);
        float c1 = __expf(t - m), c2 = __expf(0.2f * t - m);

        float p0 = preB[cc][l],  p1 = preB[cc][l + 32],  pS = preB[cc][64];
        float s0 = sufA[ccp][l], s1 = sufA[ccp][l + 32], sS = sufA[ccp][64];
#pragma unroll
        for (int q = 0; q < 8; q++) {
            int j = cc * 8 + q;
            if (j < 512) {
                const float* prow = base + (size_t)perm[j] * istride;
                float v0 = prow[l], v1 = prow[l + 32];
                if (j < K) {
                    float wgt = Bc[j];
                    p0 += wgt * v0; p1 += wgt * v1; pS += wgt;
                } else {
                    float wgt = Ac[j];
                    s0 += wgt * v0; s1 += wgt * v1; sS += wgt;
                }
            }
        }
        float inv = 1.f / (c1 * sS + c2 * pS);
        float r0 = (c1 * s0 + c2 * p0) * inv;
        float r1 = (c1 * s1 + c2 * p1) * inv;
        if (doElu) {
            r0 = (r0 > 0.f) ? r0 : (__expf(r0) - 1.f);
            r1 = (r1 > 0.f) ? r1 : (__expf(r1) - 1.f);
        }
        size_t oidx = obase + (size_t)n * istride;
        __nv_bfloat16 h0, l0, h1, l1;
        split_bf16(r0, h0, l0);
        split_bf16(r1, h1, l1);
        outh[oidx + l] = h0;      outl[oidx + l] = l0;
        outh[oidx + l + 32] = h1; outl[oidx + l + 32] = l1;
    }
}

// ===================== fc1 (mma): z(32x32768) @ fc1_w(32768x256), split-K x128 =====================
__global__ __launch_bounds__(256) void fc1_mma(const float* __restrict__ w) {
    __shared__ __align__(16) __nv_bfloat16 Ash[32][40], Asl[32][40];
    __shared__ __align__(16) __nv_bfloat16 Bh[256][40], Bl[256][40];
    int tid = threadIdx.x;
    int kb0 = blockIdx.x * 256;
    int wr = tid >> 5, lane = tid & 31;
    int g = lane >> 2, tig = lane & 3;

    float acc[2][4][4];
#pragma unroll
    for (int a = 0; a < 2; a++)
#pragma unroll
        for (int b = 0; b < 4; b++)
#pragma unroll
            for (int c = 0; c < 4; c++) acc[a][b][c] = 0.f;

    for (int ch = 0; ch < 8; ch++) {
        int kb = kb0 + ch * 32;
        if (ch) __syncthreads();
        // A chunk 32x32 (both arrays via 256 threads)
        {
            int idx = tid & 127;
            int m = idx >> 2, kg = (idx & 3) * 8;
            if (tid < 128)
                *(uint4*)&Ash[m][kg] = *(const uint4*)(g_zh + (size_t)m * 32768 + kb + kg);
            else
                *(uint4*)&Asl[m][kg] = *(const uint4*)(g_zl + (size_t)m * 32768 + kb + kg);
        }
        // B chunk 32k x 256n : split + transposed store
#pragma unroll
        for (int r = 0; r < 8; r++) {
            int idx = tid + r * 256;
            int k = idx >> 6, n4 = (idx & 63) * 4;
            float4 v = *(const float4*)(w + (size_t)(kb + k) * 256 + n4);
            __nv_bfloat16 h, l2;
            split_bf16(v.x, h, l2); Bh[n4 + 0][k] = h; Bl[n4 + 0][k] = l2;
            split_bf16(v.y, h, l2); Bh[n4 + 1][k] = h; Bl[n4 + 1][k] = l2;
            split_bf16(v.z, h, l2); Bh[n4 + 2][k] = h; Bl[n4 + 2][k] = l2;
            split_bf16(v.w, h, l2); Bh[n4 + 3][k] = h; Bl[n4 + 3][k] = l2;
        }
        __syncthreads();

#pragma unroll
        for (int ks = 0; ks < 32; ks += 16) {
            int cA = ks + 2 * tig;
            uint32_t ah[2][4], al[2][4];
#pragma unroll
            for (int mt = 0; mt < 2; mt++) {
                int r0 = mt * 16 + g;
                ah[mt][0] = *(uint32_t*)&Ash[r0][cA];
                ah[mt][1] = *(uint32_t*)&Ash[r0 + 8][cA];
                ah[mt][2] = *(uint32_t*)&Ash[r0][cA + 8];
                ah[mt][3] = *(uint32_t*)&Ash[r0 + 8][cA + 8];
                al[mt][0] = *(uint32_t*)&Asl[r0][cA];
                al[mt][1] = *(uint32_t*)&Asl[r0 + 8][cA];
                al[mt][2] = *(uint32_t*)&Asl[r0][cA + 8];
                al[mt][3] = *(uint32_t*)&Asl[r0 + 8][cA + 8];
            }
#pragma unroll
            for (int nt = 0; nt < 4; nt++) {
                int n = wr * 32 + nt * 8 + g;
                uint32_t bh0 = *(uint32_t*)&Bh[n][cA], bh1 = *(uint32_t*)&Bh[n][cA + 8];
                uint32_t bl0 = *(uint32_t*)&Bl[n][cA], bl1 = *(uint32_t*)&Bl[n][cA + 8];
#pragma unroll
                for (int mt = 0; mt < 2; mt++) {
                    mma_bf16(acc[mt][nt], ah[mt][0], ah[mt][1], ah[mt][2], ah[mt][3], bh0, bh1);
                    mma_bf16(acc[mt][nt], ah[mt][0], ah[mt][1], ah[mt][2], ah[mt][3], bl0, bl1);
                    mma_bf16(acc[mt][nt], al[mt][0], al[mt][1], al[mt][2], al[mt][3], bh0, bh1);
                }
            }
        }
    }
#pragma unroll
    for (int mt = 0; mt < 2; mt++)
#pragma unroll
        for (int nt = 0; nt < 4; nt++) {
            int row = mt * 16 + g;
            int cb = wr * 32 + nt * 8 + 2 * tig;
            *(float2*)&g_part[(size_t)blockIdx.x * 8192 + row * 256 + cb] =
                make_float2(acc[mt][nt][0], acc[mt][nt][1]);
            *(float2*)&g_part[(size_t)blockIdx.x * 8192 + (row + 8) * 256 + cb] =
                make_float2(acc[mt][nt][2], acc[mt][nt][3]);
        }
}

__global__ void fc1_reduce_kernel(const float* __restrict__ bias) {
    int idx = blockIdx.x * 256 + threadIdx.x;   // 0..8191
    float s = bias[idx & 255];
    for (int q = 0; q < 128; q++) s += g_part[q * 8192 + idx];
    g_z1[idx] = fmaxf(s, 0.f);
}

__global__ __launch_bounds__(256) void fc2_kernel(const float* __restrict__ w,
                                                  const float* __restrict__ bias) {
    __shared__ float zs[32 * 260];
    int tid = threadIdx.x;
    for (int i = tid; i < 8192; i += 256) zs[(i >> 8) * 260 + (i & 255)] = g_z1[i];
    __syncthreads();
    int c = blockIdx.x * 8 + (tid & 7);
    int r = tid >> 3;
    float acc = bias[c];
#pragma unroll 8
    for (int k = 0; k < 256; k++) acc += zs[r * 260 + k] * w[k * 256 + c];
    g_z2[r * 256 + c] = fmaxf(acc, 0.f);
}

__global__ void fc3_kernel(const float* __restrict__ w, const float* __restrict__ bias,
                           float* __restrict__ outp) {
    int tid = threadIdx.x;       // 256 threads = 128 (r,a) pairs x 2-way k split
    int p = tid >> 1, half = tid & 1;
    int r = p >> 2, a = p & 3;
    float acc = 0.f;
    int kb = half * 128;
#pragma unroll 8
    for (int k = 0; k < 128; k++) acc += g_z2[r * 256 + kb + k] * w[(kb + k) * 4 + a];
    acc += __shfl_xor_sync(0xffffffffu, acc, 1);
    if (half == 0) outp[r * 4 + a] = tanhf(acc + bias[a]);   // MAX_ACTION = 1.0
}

// ===================== launch =====================
extern "C" void kernel_launch(void* const* d_in, const int* in_sizes, int n_in,
                              void* d_out, int out_size) {
    const float* state     = (const float*)d_in[0];
    const float* W_heads   = (const float*)d_in[1];
    const float* a_src     = (const float*)d_in[2];
    const float* a_dst     = (const float*)d_in[3];
    const float* W_out     = (const float*)d_in[4];
    const float* a_out_src = (const float*)d_in[5];
    const float* a_out_dst = (const float*)d_in[6];
    const float* fc1_w     = (const float*)d_in[7];
    const float* fc1_b     = (const float*)d_in[8];
    const float* fc2_w     = (const float*)d_in[9];
    const float* fc2_b     = (const float*)d_in[10];
    const float* fc3_w     = (const float*)d_in[11];
    const float* fc3_b     = (const float*)d_in[12];
    float* out = (float*)d_out;

    prep_split<<<4352, 256>>>(state, W_heads, W_out);
    gemm1_mma<<<dim3(4, 128), 256>>>();
    attend_kernel<<<dim3(8, 32, 1), 1024>>>(1, 512, a_src, a_dst);         // 256 blocks
    gemm2_mma<<<128, 256>>>();
    attend_kernel<<<dim3(1, 32, 4), 1024>>>(2, 128, a_out_src, a_out_dst); // 128 blocks
    fc1_mma<<<128, 256>>>(fc1_w);
    fc1_reduce_kernel<<<32, 256>>>(fc1_b);
    fc2_kernel<<<32, 256>>>(fc2_w, fc2_b);
    fc3_kernel<<<1, 256>>>(fc3_w, fc3_b, out);
}

// round 9
// speedup vs baseline: 3.2117x; 1.1268x over previous
#include <cuda_runtime.h>
#include <cuda_bf16.h>
#include <cstdint>
#include <cstddef>

#define B_ 32
#define N_ 512
#define H_ 8
#define RTOT (B_ * N_)   // 16384

// ----------------- static device scratch (no allocation) -----------------
__device__ float g_Wh [(size_t)RTOT * 512];            // layer1 Wh fp32
__device__ __nv_bfloat16 g_xh[(size_t)RTOT * 512];     // layer1 out split
__device__ __nv_bfloat16 g_xl[(size_t)RTOT * 512];
__device__ float g_Wh2[(size_t)RTOT * 64];             // layer2 Wh2 fp32
__device__ __nv_bfloat16 g_zh[(size_t)RTOT * 64];      // layer2 out split (z 32x32768)
__device__ __nv_bfloat16 g_zl[(size_t)RTOT * 64];
__device__ __nv_bfloat16 g_sth[1048576], g_stl[1048576];   // state split
__device__ __nv_bfloat16 g_whTh[32768], g_whTl[32768];     // W_heads split, transposed [n=h*64+o][k]
__device__ __nv_bfloat16 g_woTh[32768], g_woTl[32768];     // W_out split, transposed [o][k]
__device__ float g_part [128 * 8192];                  // fc1 split-K partials
__device__ float g_part2[8 * 8192];
__device__ float g_z1[8192];
__device__ float g_z2[8192];

// ----------------- helpers -----------------
__device__ __forceinline__ void mma_bf16(float* c, uint32_t a0, uint32_t a1,
                                         uint32_t a2, uint32_t a3,
                                         uint32_t b0, uint32_t b1) {
    asm volatile(
        "mma.sync.aligned.m16n8k16.row.col.f32.bf16.bf16.f32 "
        "{%0,%1,%2,%3}, {%4,%5,%6,%7}, {%8,%9}, {%0,%1,%2,%3};\n"
        : "+f"(c[0]), "+f"(c[1]), "+f"(c[2]), "+f"(c[3])
        : "r"(a0), "r"(a1), "r"(a2), "r"(a3), "r"(b0), "r"(b1));
}

__device__ __forceinline__ void split_bf16(float x, __nv_bfloat16& h, __nv_bfloat16& l) {
    h = __float2bfloat16(x);
    l = __float2bfloat16(x - __bfloat162float(h));
}

__device__ __forceinline__ void cp16(void* smem, const void* gmem) {
    uint32_t s = (uint32_t)__cvta_generic_to_shared(smem);
    asm volatile("cp.async.ca.shared.global [%0], [%1], 16;\n" :: "r"(s), "l"(gmem));
}
#define CP_COMMIT  asm volatile("cp.async.commit_group;\n" ::: "memory")
#define CP_WAIT0   asm volatile("cp.async.wait_group 0;\n" ::: "memory")
#define CP_WAIT1   asm volatile("cp.async.wait_group 1;\n" ::: "memory")

// ===================== prep: split + transpose inputs =====================
__global__ void prep_split(const float* __restrict__ st, const float* __restrict__ wh,
                           const float* __restrict__ wo) {
    int i = blockIdx.x * 256 + threadIdx.x;
    if (i < 1048576) {
        __nv_bfloat16 h, l; split_bf16(st[i], h, l);
        g_sth[i] = h; g_stl[i] = l;
    } else if (i < 1048576 + 32768) {
        int j = i - 1048576;          // j = n*64 + k, n = h*64+o
        int n = j >> 6, k = j & 63;
        int hh = n >> 6, o = n & 63;
        __nv_bfloat16 h, l; split_bf16(wh[hh * 4096 + k * 64 + o], h, l);
        g_whTh[j] = h; g_whTl[j] = l;
    } else {
        int j = i - 1048576 - 32768;  // j = o*512 + k
        int o = j >> 9, k = j & 511;
        __nv_bfloat16 h, l; split_bf16(wo[k * 64 + o], h, l);
        g_woTh[j] = h; g_woTl[j] = l;
    }
}

// ===================== GEMM1 (mma): state(16384x64) @ Wheads(64x512) -> g_Wh =====================
__global__ __launch_bounds__(256) void gemm1_mma() {
    __shared__ __align__(16) __nv_bfloat16 Ah[128][40], Al[128][40];
    __shared__ __align__(16) __nv_bfloat16 Bh[128][40], Bl[128][40];
    int tid = threadIdx.x;
    int c0 = blockIdx.x * 128;
    int m0 = blockIdx.y * 128;
    int w = tid >> 5, lane = tid & 31;
    int g = lane >> 2, tig = lane & 3;
    int wm = w & 3, wn = w >> 2;

    float acc[2][8][4];
#pragma unroll
    for (int a = 0; a < 2; a++)
#pragma unroll
        for (int b = 0; b < 8; b++)
#pragma unroll
            for (int c = 0; c < 4; c++) acc[a][b][c] = 0.f;

    for (int kc = 0; kc < 64; kc += 32) {
        if (kc) __syncthreads();
        // A chunk 128x32, B chunk 128n x 32k  — straight cp.async copies
#pragma unroll
        for (int r = 0; r < 2; r++) {
            int idx = tid + r * 256;
            int m = idx >> 2, kg = (idx & 3) * 8;
            cp16(&Ah[m][kg], g_sth + (size_t)(m0 + m) * 64 + kc + kg);
            cp16(&Al[m][kg], g_stl + (size_t)(m0 + m) * 64 + kc + kg);
            cp16(&Bh[m][kg], g_whTh + (size_t)(c0 + m) * 64 + kc + kg);
            cp16(&Bl[m][kg], g_whTl + (size_t)(c0 + m) * 64 + kc + kg);
        }
        CP_COMMIT;
        CP_WAIT0;
        __syncthreads();

#pragma unroll
        for (int ks = 0; ks < 32; ks += 16) {
            uint32_t ah[2][4], al[2][4];
            int cA = ks + 2 * tig;
#pragma unroll
            for (int tm = 0; tm < 2; tm++) {
                int r0 = wm * 32 + tm * 16 + g;
                ah[tm][0] = *(uint32_t*)&Ah[r0][cA];
                ah[tm][1] = *(uint32_t*)&Ah[r0 + 8][cA];
                ah[tm][2] = *(uint32_t*)&Ah[r0][cA + 8];
                ah[tm][3] = *(uint32_t*)&Ah[r0 + 8][cA + 8];
                al[tm][0] = *(uint32_t*)&Al[r0][cA];
                al[tm][1] = *(uint32_t*)&Al[r0 + 8][cA];
                al[tm][2] = *(uint32_t*)&Al[r0][cA + 8];
                al[tm][3] = *(uint32_t*)&Al[r0 + 8][cA + 8];
            }
#pragma unroll
            for (int tn = 0; tn < 8; tn++) {
                int n = wn * 64 + tn * 8 + g;
                uint32_t bh0 = *(uint32_t*)&Bh[n][cA], bh1 = *(uint32_t*)&Bh[n][cA + 8];
                uint32_t bl0 = *(uint32_t*)&Bl[n][cA], bl1 = *(uint32_t*)&Bl[n][cA + 8];
#pragma unroll
                for (int tm = 0; tm < 2; tm++) {
                    mma_bf16(acc[tm][tn], ah[tm][0], ah[tm][1], ah[tm][2], ah[tm][3], bh0, bh1);
                    mma_bf16(acc[tm][tn], ah[tm][0], ah[tm][1], ah[tm][2], ah[tm][3], bl0, bl1);
                    mma_bf16(acc[tm][tn], al[tm][0], al[tm][1], al[tm][2], al[tm][3], bh0, bh1);
                }
            }
        }
    }
#pragma unroll
    for (int tm = 0; tm < 2; tm++)
#pragma unroll
        for (int tn = 0; tn < 8; tn++) {
            int r0 = m0 + wm * 32 + tm * 16 + g;
            int c = c0 + wn * 64 + tn * 8 + 2 * tig;
            *(float2*)&g_Wh[(size_t)r0 * 512 + c] = make_float2(acc[tm][tn][0], acc[tm][tn][1]);
            *(float2*)&g_Wh[(size_t)(r0 + 8) * 512 + c] = make_float2(acc[tm][tn][2], acc[tm][tn][3]);
        }
}

// ===================== GEMM2 (mma): g_x(16384x512) @ W_out(512x64) -> g_Wh2 =====================
// M-tile 64, grid 256, double-buffered cp.async pipeline, K-chunks of 32.
__global__ __launch_bounds__(256) void gemm2_mma() {
    __shared__ __align__(16) __nv_bfloat16 Ah[2][64][40], Al[2][64][40];
    __shared__ __align__(16) __nv_bfloat16 Bh[2][64][40], Bl[2][64][40];
    int tid = threadIdx.x;
    int m0 = blockIdx.x * 64;
    int w = tid >> 5, lane = tid & 31;
    int g = lane >> 2, tig = lane & 3;
    int wm = w & 3;     // 4 m-tiles of 16 rows
    int wn = w >> 2;    // 2 n-tiles of 32 cols

    float acc[4][4];
#pragma unroll
    for (int b = 0; b < 4; b++)
#pragma unroll
        for (int c = 0; c < 4; c++) acc[b][c] = 0.f;

    int mA = tid >> 2, kgA = (tid & 3) * 8;   // 64 rows x 4 quads of 8 cols

    // prologue: chunk 0
    cp16(&Ah[0][mA][kgA], g_xh + (size_t)(m0 + mA) * 512 + kgA);
    cp16(&Al[0][mA][kgA], g_xl + (size_t)(m0 + mA) * 512 + kgA);
    cp16(&Bh[0][mA][kgA], g_woTh + (size_t)mA * 512 + kgA);
    cp16(&Bl[0][mA][kgA], g_woTl + (size_t)mA * 512 + kgA);
    CP_COMMIT;

    for (int ch = 0; ch < 16; ch++) {
        if (ch < 15) {
            int kc = (ch + 1) * 32;
            int nb = (ch + 1) & 1;
            cp16(&Ah[nb][mA][kgA], g_xh + (size_t)(m0 + mA) * 512 + kc + kgA);
            cp16(&Al[nb][mA][kgA], g_xl + (size_t)(m0 + mA) * 512 + kc + kgA);
            cp16(&Bh[nb][mA][kgA], g_woTh + (size_t)mA * 512 + kc + kgA);
            cp16(&Bl[nb][mA][kgA], g_woTl + (size_t)mA * 512 + kc + kgA);
            CP_COMMIT;
            CP_WAIT1;
        } else {
            CP_WAIT0;
        }
        __syncthreads();
        int buf = ch & 1;

#pragma unroll
        for (int ks = 0; ks < 32; ks += 16) {
            int cA = ks + 2 * tig;
            int r0 = wm * 16 + g;
            uint32_t ah0 = *(uint32_t*)&Ah[buf][r0][cA],     ah1 = *(uint32_t*)&Ah[buf][r0 + 8][cA];
            uint32_t ah2 = *(uint32_t*)&Ah[buf][r0][cA + 8], ah3 = *(uint32_t*)&Ah[buf][r0 + 8][cA + 8];
            uint32_t al0 = *(uint32_t*)&Al[buf][r0][cA],     al1 = *(uint32_t*)&Al[buf][r0 + 8][cA];
            uint32_t al2 = *(uint32_t*)&Al[buf][r0][cA + 8], al3 = *(uint32_t*)&Al[buf][r0 + 8][cA + 8];
#pragma unroll
            for (int nt = 0; nt < 4; nt++) {
                int n = wn * 32 + nt * 8 + g;
                uint32_t bh0 = *(uint32_t*)&Bh[buf][n][cA], bh1 = *(uint32_t*)&Bh[buf][n][cA + 8];
                uint32_t bl0 = *(uint32_t*)&Bl[buf][n][cA], bl1 = *(uint32_t*)&Bl[buf][n][cA + 8];
                mma_bf16(acc[nt], ah0, ah1, ah2, ah3, bh0, bh1);
                mma_bf16(acc[nt], ah0, ah1, ah2, ah3, bl0, bl1);
                mma_bf16(acc[nt], al0, al1, al2, al3, bh0, bh1);
            }
        }
        __syncthreads();
    }
#pragma unroll
    for (int nt = 0; nt < 4; nt++) {
        int r0 = m0 + wm * 16 + g;
        int c = wn * 32 + nt * 8 + 2 * tig;
        *(float2*)&g_Wh2[(size_t)r0 * 64 + c] = make_float2(acc[nt][0], acc[nt][1]);
        *(float2*)&g_Wh2[(size_t)(r0 + 8) * 64 + c] = make_float2(acc[nt][2], acc[nt][3]);
    }
}

// ===================== factorized GAT attention (1024 threads, row-split) =====================
// e[i,j] = leaky_relu(s_i + d_j): positive set is a suffix in d-sorted order.
__global__ __launch_bounds__(1024) void attend_kernel(int layer, int rowsPerBlock,
                                                      const float* __restrict__ asrc,
                                                      const float* __restrict__ adst) {
    __shared__ float dv[512];
    __shared__ int   perm[512];
    __shared__ float ssrc[512];
    __shared__ float Ac[512];
    __shared__ float Bc[512];
    __shared__ float preB[65][65];   // [c][o], o=0..63 cols, o=64 scalar
    __shared__ float sufA[65][65];
    __shared__ float gsum[8][65];
    __shared__ float sAs[64], sAd[64];
    __shared__ int   Kv[512];

    const float* Wh = (layer == 1) ? g_Wh : g_Wh2;
    __nv_bfloat16* outh = (layer == 1) ? g_xh : g_zh;
    __nv_bfloat16* outl = (layer == 1) ? g_xl : g_zl;
    const int istride = (layer == 1) ? 512 : 64;
    const int aStride = (layer == 1) ? 64 : 0;
    const int doElu   = (layer == 1) ? 1 : 0;

    int tid = threadIdx.x;
    int h = blockIdx.x, b = blockIdx.y;
    int rStart = blockIdx.z * rowsPerBlock;
    const float* base = Wh + (size_t)b * 512 * istride + h * 64;
    size_t obase = (size_t)b * 512 * istride + h * 64;

    if (tid < 64) { sAs[tid] = asrc[h * aStride + tid]; sAd[tid] = adst[h * aStride + tid]; }
    __syncthreads();

    int warp = tid >> 5, l = tid & 31;
    // s_src / d for ALL 512 rows (32 warps x 16 rows)
    for (int n = warp * 16; n < warp * 16 + 16; n++) {
        const float* row = base + (size_t)n * istride;
        float v0 = row[l], v1 = row[l + 32];
        float ps = v0 * sAs[l] + v1 * sAs[l + 32];
        float pd = v0 * sAd[l] + v1 * sAd[l + 32];
#pragma unroll
        for (int off = 16; off; off >>= 1) {
            ps += __shfl_xor_sync(0xffffffffu, ps, off);
            pd += __shfl_xor_sync(0xffffffffu, pd, off);
        }
        if (l == 0) { ssrc[n] = ps; dv[n] = pd; perm[n] = n; }
    }
    __syncthreads();

    // register-resident bitonic sort on tid<512 (shfl j<32, smem exchange j>=32)
    float key = (tid < 512) ? dv[tid] : 0.f;
    int   pm  = (tid < 512) ? perm[tid] : 0;
    for (int k = 2; k <= 512; k <<= 1) {
        for (int j = k >> 1; j > 0; j >>= 1) {
            if (j >= 32) {
                __syncthreads();
                if (tid < 512) { dv[tid] = key; perm[tid] = pm; }
                __syncthreads();
                if (tid < 512) {
                    float pk = dv[tid ^ j]; int pp = perm[tid ^ j];
                    bool up = ((tid & k) == 0);
                    bool iLower = ((tid & j) == 0);
                    bool wantMin = (up == iLower);
                    if (wantMin ? (pk < key) : (pk > key)) { key = pk; pm = pp; }
                }
            } else if (tid < 512) {
                float pk = __shfl_xor_sync(0xffffffffu, key, j);
                int   pp = __shfl_xor_sync(0xffffffffu, pm, j);
                bool up = ((tid & k) == 0);
                bool iLower = ((tid & j) == 0);
                bool wantMin = (up == iLower);
                if (wantMin ? (pk < key) : (pk > key)) { key = pk; pm = pp; }
            }
        }
    }
    __syncthreads();
    if (tid < 512) { dv[tid] = key; perm[tid] = pm; }
    __syncthreads();

    float dm = dv[511];
    if (tid < 512) {
        float d = key - dm;
        Ac[tid] = __expf(d);
        Bc[tid] = __expf(0.2f * d);
    }
    if (tid < 65) { preB[0][tid] = 0.f; sufA[64][tid] = 0.f; }
    __syncthreads();

    // chunk sums (64 chunks of 8, 65 "columns"; col 64 carries scalar sums)
    for (int it = tid; it < 64 * 65; it += 1024) {
        int c = it / 65;
        int o = it - c * 65;
        float sA = 0.f, sB = 0.f;
#pragma unroll
        for (int q = 0; q < 8; q++) {
            int j = c * 8 + q;
            float v = (o < 64) ? base[(size_t)perm[j] * istride + o] : 1.0f;
            sA += Ac[j] * v;
            sB += Bc[j] * v;
        }
        sufA[c][o] = sA;
        preB[c + 1][o] = sB;
    }
    __syncthreads();

    // two-level prefix scan of preB over c = 1..64
    for (int it = tid; it < 8 * 65; it += 1024) {
        int g = it / 65, o = it - g * 65;
        float run = 0.f;
#pragma unroll
        for (int k2 = 0; k2 < 8; k2++) {
            int c = g * 8 + 1 + k2;
            run += preB[c][o];
            preB[c][o] = run;
        }
        gsum[g][o] = run;
    }
    __syncthreads();
    if (tid < 65) {
        int o = tid;
        float run = 0.f;
#pragma unroll
        for (int g = 0; g < 8; g++) { float t = gsum[g][o]; gsum[g][o] = run; run += t; }
    }
    __syncthreads();
    for (int it = tid; it < 8 * 65; it += 1024) {
        int g = it / 65, o = it - g * 65;
        float add = gsum[g][o];
#pragma unroll
        for (int k2 = 0; k2 < 8; k2++) preB[g * 8 + 1 + k2][o] += add;
    }
    __syncthreads();

    // two-level suffix scan of sufA over c = 63..0
    for (int it = tid; it < 8 * 65; it += 1024) {
        int g = it / 65, o = it - g * 65;
        float run = 0.f;
#pragma unroll
        for (int k2 = 7; k2 >= 0; k2--) {
            int c = g * 8 + k2;
            run += sufA[c][o];
            sufA[c][o] = run;
        }
        gsum[g][o] = run;
    }
    __syncthreads();
    if (tid < 65) {
        int o = tid;
        float run = 0.f;
#pragma unroll
        for (int g = 7; g >= 0; g--) { float t = gsum[g][o]; gsum[g][o] = run; run += t; }
    }
    __syncthreads();
    for (int it = tid; it < 8 * 65; it += 1024) {
        int g = it / 65, o = it - g * 65;
        float add = gsum[g][o];
#pragma unroll
        for (int k2 = 0; k2 < 8; k2++) sufA[g * 8 + k2][o] += add;
    }
    __syncthreads();

    // parallel binary searches for this block's row slice
    if (tid < rowsPerBlock) {
        float negs = -ssrc[rStart + tid];
        int lo = 0, hi = 512;
        while (lo < hi) { int mid = (lo + hi) >> 1; if (dv[mid] <= negs) lo = mid + 1; else hi = mid; }
        Kv[tid] = lo;
    }
    __syncthreads();

    // row outputs: warp per row, strided over 32 warps; emit bf16 h/l split
    for (int ni = warp; ni < rowsPerBlock; ni += 32) {
        int n = rStart + ni;
        int K = Kv[ni];
        int cc = K >> 3;
        int ccp = (cc < 64) ? cc + 1 : 64;
        float t = ssrc[n] + dm;
        float m = fmaxf(t, 0.2f * t);
        float c1 = __expf(t - m), c2 = __expf(0.2f * t - m);

        float p0 = preB[cc][l],  p1 = preB[cc][l + 32],  pS = preB[cc][64];
        float s0 = sufA[ccp][l], s1 = sufA[ccp][l + 32], sS = sufA[ccp][64];
#pragma unroll
        for (int q = 0; q < 8; q++) {
            int j = cc * 8 + q;
            if (j < 512) {
                const float* prow = base + (size_t)perm[j] * istride;
                float v0 = prow[l], v1 = prow[l + 32];
                if (j < K) {
                    float wgt = Bc[j];
                    p0 += wgt * v0; p1 += wgt * v1; pS += wgt;
                } else {
                    float wgt = Ac[j];
                    s0 += wgt * v0; s1 += wgt * v1; sS += wgt;
                }
            }
        }
        float inv = 1.f / (c1 * sS + c2 * pS);
        float r0 = (c1 * s0 + c2 * p0) * inv;
        float r1 = (c1 * s1 + c2 * p1) * inv;
        if (doElu) {
            r0 = (r0 > 0.f) ? r0 : (__expf(r0) - 1.f);
            r1 = (r1 > 0.f) ? r1 : (__expf(r1) - 1.f);
        }
        size_t oidx = obase + (size_t)n * istride;
        __nv_bfloat16 h0, l0, h1, l1;
        split_bf16(r0, h0, l0);
        split_bf16(r1, h1, l1);
        outh[oidx + l] = h0;      outl[oidx + l] = l0;
        outh[oidx + l + 32] = h1; outl[oidx + l + 32] = l1;
    }
}

// ===================== fc1 (mma): z(32x32768) @ fc1_w(32768x256), split-K x128 =====================
__global__ __launch_bounds__(256) void fc1_mma(const float* __restrict__ w) {
    __shared__ __align__(16) __nv_bfloat16 Ash[32][40], Asl[32][40];
    __shared__ __align__(16) __nv_bfloat16 Bh[256][40], Bl[256][40];
    int tid = threadIdx.x;
    int kb0 = blockIdx.x * 256;
    int wr = tid >> 5, lane = tid & 31;
    int g = lane >> 2, tig = lane & 3;

    float acc[2][4][4];
#pragma unroll
    for (int a = 0; a < 2; a++)
#pragma unroll
        for (int b = 0; b < 4; b++)
#pragma unroll
            for (int c = 0; c < 4; c++) acc[a][b][c] = 0.f;

    for (int ch = 0; ch < 8; ch++) {
        int kb = kb0 + ch * 32;
        if (ch) __syncthreads();
        // A chunk 32x32 (both arrays via 256 threads)
        {
            int idx = tid & 127;
            int m = idx >> 2, kg = (idx & 3) * 8;
            if (tid < 128)
                cp16(&Ash[m][kg], g_zh + (size_t)m * 32768 + kb + kg);
            else
                cp16(&Asl[m][kg], g_zl + (size_t)m * 32768 + kb + kg);
        }
        CP_COMMIT;
        // B chunk 32k x 256n : split + transposed store
#pragma unroll
        for (int r = 0; r < 8; r++) {
            int idx = tid + r * 256;
            int k = idx >> 6, n4 = (idx & 63) * 4;
            float4 v = *(const float4*)(w + (size_t)(kb + k) * 256 + n4);
            __nv_bfloat16 h, l2;
            split_bf16(v.x, h, l2); Bh[n4 + 0][k] = h; Bl[n4 + 0][k] = l2;
            split_bf16(v.y, h, l2); Bh[n4 + 1][k] = h; Bl[n4 + 1][k] = l2;
            split_bf16(v.z, h, l2); Bh[n4 + 2][k] = h; Bl[n4 + 2][k] = l2;
            split_bf16(v.w, h, l2); Bh[n4 + 3][k] = h; Bl[n4 + 3][k] = l2;
        }
        CP_WAIT0;
        __syncthreads();

#pragma unroll
        for (int ks = 0; ks < 32; ks += 16) {
            int cA = ks + 2 * tig;
            uint32_t ah[2][4], al[2][4];
#pragma unroll
            for (int mt = 0; mt < 2; mt++) {
                int r0 = mt * 16 + g;
                ah[mt][0] = *(uint32_t*)&Ash[r0][cA];
                ah[mt][1] = *(uint32_t*)&Ash[r0 + 8][cA];
                ah[mt][2] = *(uint32_t*)&Ash[r0][cA + 8];
                ah[mt][3] = *(uint32_t*)&Ash[r0 + 8][cA + 8];
                al[mt][0] = *(uint32_t*)&Asl[r0][cA];
                al[mt][1] = *(uint32_t*)&Asl[r0 + 8][cA];
                al[mt][2] = *(uint32_t*)&Asl[r0][cA + 8];
                al[mt][3] = *(uint32_t*)&Asl[r0 + 8][cA + 8];
            }
#pragma unroll
            for (int nt = 0; nt < 4; nt++) {
                int n = wr * 32 + nt * 8 + g;
                uint32_t bh0 = *(uint32_t*)&Bh[n][cA], bh1 = *(uint32_t*)&Bh[n][cA + 8];
                uint32_t bl0 = *(uint32_t*)&Bl[n][cA], bl1 = *(uint32_t*)&Bl[n][cA + 8];
#pragma unroll
                for (int mt = 0; mt < 2; mt++) {
                    mma_bf16(acc[mt][nt], ah[mt][0], ah[mt][1], ah[mt][2], ah[mt][3], bh0, bh1);
                    mma_bf16(acc[mt][nt], ah[mt][0], ah[mt][1], ah[mt][2], ah[mt][3], bl0, bl1);
                    mma_bf16(acc[mt][nt], al[mt][0], al[mt][1], al[mt][2], al[mt][3], bh0, bh1);
                }
            }
        }
    }
#pragma unroll
    for (int mt = 0; mt < 2; mt++)
#pragma unroll
        for (int nt = 0; nt < 4; nt++) {
            int row = mt * 16 + g;
            int cb = wr * 32 + nt * 8 + 2 * tig;
            *(float2*)&g_part[(size_t)blockIdx.x * 8192 + row * 256 + cb] =
                make_float2(acc[mt][nt][0], acc[mt][nt][1]);
            *(float2*)&g_part[(size_t)blockIdx.x * 8192 + (row + 8) * 256 + cb] =
                make_float2(acc[mt][nt][2], acc[mt][nt][3]);
        }
}

__global__ void fc1_reduce1() {
    int sg = blockIdx.x >> 5;                      // 0..7
    int idx = (blockIdx.x & 31) * 256 + threadIdx.x;
    float s = 0.f;
#pragma unroll
    for (int q = 0; q < 16; q++) s += g_part[(size_t)(sg * 16 + q) * 8192 + idx];
    g_part2[sg * 8192 + idx] = s;
}

__global__ void fc1_reduce2(const float* __restrict__ bias) {
    int idx = blockIdx.x * 256 + threadIdx.x;      // 0..8191
    float s = bias[idx & 255];
#pragma unroll
    for (int q = 0; q < 8; q++) s += g_part2[q * 8192 + idx];
    g_z1[idx] = fmaxf(s, 0.f);
}

__global__ __launch_bounds__(256) void fc2_kernel(const float* __restrict__ w,
                                                  const float* __restrict__ bias) {
    __shared__ float zs[32 * 260];
    int tid = threadIdx.x;
    for (int i = tid; i < 8192; i += 256) zs[(i >> 8) * 260 + (i & 255)] = g_z1[i];
    __syncthreads();
    int c = blockIdx.x * 8 + (tid & 7);
    int r = tid >> 3;
    float acc = bias[c];
#pragma unroll 8
    for (int k = 0; k < 256; k++) acc += zs[r * 260 + k] * w[k * 256 + c];
    g_z2[r * 256 + c] = fmaxf(acc, 0.f);
}

__global__ void fc3_kernel(const float* __restrict__ w, const float* __restrict__ bias,
                           float* __restrict__ outp) {
    int tid = threadIdx.x;       // 256 threads = 128 (r,a) pairs x 2-way k split
    int p = tid >> 1, half = tid & 1;
    int r = p >> 2, a = p & 3;
    float acc = 0.f;
    int kb = half * 128;
#pragma unroll 8
    for (int k = 0; k < 128; k++) acc += g_z2[r * 256 + kb + k] * w[(kb + k) * 4 + a];
    acc += __shfl_xor_sync(0xffffffffu, acc, 1);
    if (half == 0) outp[r * 4 + a] = tanhf(acc + bias[a]);   // MAX_ACTION = 1.0
}

// ===================== launch =====================
extern "C" void kernel_launch(void* const* d_in, const int* in_sizes, int n_in,
                              void* d_out, int out_size) {
    const float* state     = (const float*)d_in[0];
    const float* W_heads   = (const float*)d_in[1];
    const float* a_src     = (const float*)d_in[2];
    const float* a_dst     = (const float*)d_in[3];
    const float* W_out     = (const float*)d_in[4];
    const float* a_out_src = (const float*)d_in[5];
    const float* a_out_dst = (const float*)d_in[6];
    const float* fc1_w     = (const float*)d_in[7];
    const float* fc1_b     = (const float*)d_in[8];
    const float* fc2_w     = (const float*)d_in[9];
    const float* fc2_b     = (const float*)d_in[10];
    const float* fc3_w     = (const float*)d_in[11];
    const float* fc3_b     = (const float*)d_in[12];
    float* out = (float*)d_out;

    prep_split<<<4352, 256>>>(state, W_heads, W_out);
    gemm1_mma<<<dim3(4, 128), 256>>>();
    attend_kernel<<<dim3(8, 32, 1), 1024>>>(1, 512, a_src, a_dst);         // 256 blocks
    gemm2_mma<<<256, 256>>>();
    attend_kernel<<<dim3(1, 32, 4), 1024>>>(2, 128, a_out_src, a_out_dst); // 128 blocks
    fc1_mma<<<128, 256>>>(fc1_w);
    fc1_reduce1<<<256, 256>>>();
    fc1_reduce2<<<32, 256>>>(fc1_b);
    fc2_kernel<<<32, 256>>>(fc2_w, fc2_b);
    fc3_kernel<<<1, 256>>>(fc3_w, fc3_b, out);
}

// round 13
// speedup vs baseline: 3.2659x; 1.0169x over previous
#include <cuda_runtime.h>
#include <cuda_bf16.h>
#include <cstdint>
#include <cstddef>

#define B_ 32
#define N_ 512
#define H_ 8
#define RTOT (B_ * N_)   // 16384

// ----------------- static device scratch (no allocation) -----------------
__device__ float g_Wh [(size_t)RTOT * 512];            // layer1 Wh fp32
__device__ __nv_bfloat16 g_xh[(size_t)RTOT * 512];     // layer1 out split
__device__ __nv_bfloat16 g_xl[(size_t)RTOT * 512];
__device__ float g_Wh2[(size_t)RTOT * 64];             // layer2 Wh2 fp32
__device__ __nv_bfloat16 g_zh[(size_t)RTOT * 64];      // layer2 out split (z 32x32768)
__device__ __nv_bfloat16 g_zl[(size_t)RTOT * 64];
__device__ __nv_bfloat16 g_sth[1048576], g_stl[1048576];   // state split
__device__ __nv_bfloat16 g_whTh[32768], g_whTl[32768];     // W_heads split, transposed [n][k]
__device__ __nv_bfloat16 g_woTh[32768], g_woTl[32768];     // W_out split, transposed [o][k]
__device__ float g_part [128 * 8192];                  // fc1 split-K partials
__device__ float g_part2[8 * 8192];
__device__ float g_z1[8192];
__device__ float g_z2[8192];

// ----------------- helpers -----------------
__device__ __forceinline__ void mma_bf16(float* c, uint32_t a0, uint32_t a1,
                                         uint32_t a2, uint32_t a3,
                                         uint32_t b0, uint32_t b1) {
    asm volatile(
        "mma.sync.aligned.m16n8k16.row.col.f32.bf16.bf16.f32 "
        "{%0,%1,%2,%3}, {%4,%5,%6,%7}, {%8,%9}, {%0,%1,%2,%3};\n"
        : "+f"(c[0]), "+f"(c[1]), "+f"(c[2]), "+f"(c[3])
        : "r"(a0), "r"(a1), "r"(a2), "r"(a3), "r"(b0), "r"(b1));
}

__device__ __forceinline__ void split_bf16(float x, __nv_bfloat16& h, __nv_bfloat16& l) {
    h = __float2bfloat16(x);
    l = __float2bfloat16(x - __bfloat162float(h));
}

__device__ __forceinline__ void cp16(void* smem, const void* gmem) {
    uint32_t s = (uint32_t)__cvta_generic_to_shared(smem);
    asm volatile("cp.async.ca.shared.global [%0], [%1], 16;\n" :: "r"(s), "l"(gmem));
}
#define CP_COMMIT  asm volatile("cp.async.commit_group;\n" ::: "memory")
#define CP_WAIT0   asm volatile("cp.async.wait_group 0;\n" ::: "memory")
#define CP_WAIT1   asm volatile("cp.async.wait_group 1;\n" ::: "memory")

// ldmatrix x4: lanes 0-7 -> rows r..r+7 @ col c; 8-15 -> r+8..r+15 @ c;
// 16-23 -> r..r+7 @ c+8; 24-31 -> r+8..r+15 @ c+8.
// Result regs = (m0,m1,m2,m3) = (a0-style, +8rows, +8cols, both).
__device__ __forceinline__ void ldsm4(uint32_t* r, uint32_t a) {
    asm volatile("ldmatrix.sync.aligned.m8n8.x4.shared.b16 {%0,%1,%2,%3}, [%4];\n"
                 : "=r"(r[0]), "=r"(r[1]), "=r"(r[2]), "=r"(r[3]) : "r"(a));
}

// per-lane (row,col) offset selector for the x4 address pattern above
__device__ __forceinline__ void ldsm_sel(int lane, int& rsel, int& csel) {
    rsel = ((lane >> 3) & 1) * 8 + (lane & 7);
    csel = (lane >> 4) * 8;
}

// ===================== prep: split + transpose inputs =====================
__global__ void prep_split(const float* __restrict__ st, const float* __restrict__ wh,
                           const float* __restrict__ wo) {
    int i = blockIdx.x * 256 + threadIdx.x;
    if (i < 1048576) {
        __nv_bfloat16 h, l; split_bf16(st[i], h, l);
        g_sth[i] = h; g_stl[i] = l;
    } else if (i < 1048576 + 32768) {
        int j = i - 1048576;          // j = n*64 + k, n = h*64+o
        int n = j >> 6, k = j & 63;
        int hh = n >> 6, o = n & 63;
        __nv_bfloat16 h, l; split_bf16(wh[hh * 4096 + k * 64 + o], h, l);
        g_whTh[j] = h; g_whTl[j] = l;
    } else {
        int j = i - 1048576 - 32768;  // j = o*512 + k
        int o = j >> 9, k = j & 511;
        __nv_bfloat16 h, l; split_bf16(wo[k * 64 + o], h, l);
        g_woTh[j] = h; g_woTl[j] = l;
    }
}

// ===================== GEMM1 (mma): state(16384x64) @ Wheads(64x512) -> g_Wh =====================
__global__ __launch_bounds__(256) void gemm1_mma() {
    __shared__ __align__(16) __nv_bfloat16 Ah[128][40], Al[128][40];
    __shared__ __align__(16) __nv_bfloat16 Bh[128][40], Bl[128][40];
    int tid = threadIdx.x;
    int c0 = blockIdx.x * 128;
    int m0 = blockIdx.y * 128;
    int w = tid >> 5, lane = tid & 31;
    int g = lane >> 2, tig = lane & 3;
    int wm = w & 3, wn = w >> 2;
    int rsel, csel; ldsm_sel(lane, rsel, csel);

    float acc[2][8][4];
#pragma unroll
    for (int a = 0; a < 2; a++)
#pragma unroll
        for (int b = 0; b < 8; b++)
#pragma unroll
            for (int c = 0; c < 4; c++) acc[a][b][c] = 0.f;

    for (int kc = 0; kc < 64; kc += 32) {
        if (kc) __syncthreads();
#pragma unroll
        for (int r = 0; r < 2; r++) {
            int idx = tid + r * 256;
            int m = idx >> 2, kg = (idx & 3) * 8;
            cp16(&Ah[m][kg], g_sth + (size_t)(m0 + m) * 64 + kc + kg);
            cp16(&Al[m][kg], g_stl + (size_t)(m0 + m) * 64 + kc + kg);
            cp16(&Bh[m][kg], g_whTh + (size_t)(c0 + m) * 64 + kc + kg);
            cp16(&Bl[m][kg], g_whTl + (size_t)(c0 + m) * 64 + kc + kg);
        }
        CP_COMMIT;
        CP_WAIT0;
        __syncthreads();

#pragma unroll
        for (int ks = 0; ks < 32; ks += 16) {
            uint32_t ah[2][4], al[2][4];
#pragma unroll
            for (int tm = 0; tm < 2; tm++) {
                int r0 = wm * 32 + tm * 16 + rsel;
                ldsm4(ah[tm], (uint32_t)__cvta_generic_to_shared(&Ah[r0][ks + csel]));
                ldsm4(al[tm], (uint32_t)__cvta_generic_to_shared(&Al[r0][ks + csel]));
            }
            uint32_t bh[4][4], bl[4][4];   // [pair][m0,m1,m2,m3]; pair covers 16 n-rows
#pragma unroll
            for (int p = 0; p < 4; p++) {
                int n0 = wn * 64 + p * 16 + rsel;
                ldsm4(bh[p], (uint32_t)__cvta_generic_to_shared(&Bh[n0][ks + csel]));
                ldsm4(bl[p], (uint32_t)__cvta_generic_to_shared(&Bl[n0][ks + csel]));
            }
#pragma unroll
            for (int tn = 0; tn < 8; tn++) {
                int p = tn >> 1, sub = tn & 1;
                uint32_t bh0 = bh[p][sub], bh1 = bh[p][sub + 2];
                uint32_t bl0 = bl[p][sub], bl1 = bl[p][sub + 2];
#pragma unroll
                for (int tm = 0; tm < 2; tm++) {
                    mma_bf16(acc[tm][tn], ah[tm][0], ah[tm][1], ah[tm][2], ah[tm][3], bh0, bh1);
                    mma_bf16(acc[tm][tn], ah[tm][0], ah[tm][1], ah[tm][2], ah[tm][3], bl0, bl1);
                    mma_bf16(acc[tm][tn], al[tm][0], al[tm][1], al[tm][2], al[tm][3], bh0, bh1);
                }
            }
        }
    }
#pragma unroll
    for (int tm = 0; tm < 2; tm++)
#pragma unroll
        for (int tn = 0; tn < 8; tn++) {
            int r0 = m0 + wm * 32 + tm * 16 + g;
            int c = c0 + wn * 64 + tn * 8 + 2 * tig;
            *(float2*)&g_Wh[(size_t)r0 * 512 + c] = make_float2(acc[tm][tn][0], acc[tm][tn][1]);
            *(float2*)&g_Wh[(size_t)(r0 + 8) * 512 + c] = make_float2(acc[tm][tn][2], acc[tm][tn][3]);
        }
}

// ===================== GEMM2 (mma): g_x(16384x512) @ W_out(512x64) -> g_Wh2 =====================
__global__ __launch_bounds__(256) void gemm2_mma() {
    __shared__ __align__(16) __nv_bfloat16 Ah[2][64][40], Al[2][64][40];
    __shared__ __align__(16) __nv_bfloat16 Bh[2][64][40], Bl[2][64][40];
    int tid = threadIdx.x;
    int m0 = blockIdx.x * 64;
    int w = tid >> 5, lane = tid & 31;
    int g = lane >> 2, tig = lane & 3;
    int wm = w & 3;     // 4 m-tiles of 16 rows
    int wn = w >> 2;    // 2 n-tiles of 32 cols
    int rsel, csel; ldsm_sel(lane, rsel, csel);

    float acc[4][4];
#pragma unroll
    for (int b = 0; b < 4; b++)
#pragma unroll
        for (int c = 0; c < 4; c++) acc[b][c] = 0.f;

    int mA = tid >> 2, kgA = (tid & 3) * 8;

    cp16(&Ah[0][mA][kgA], g_xh + (size_t)(m0 + mA) * 512 + kgA);
    cp16(&Al[0][mA][kgA], g_xl + (size_t)(m0 + mA) * 512 + kgA);
    cp16(&Bh[0][mA][kgA], g_woTh + (size_t)mA * 512 + kgA);
    cp16(&Bl[0][mA][kgA], g_woTl + (size_t)mA * 512 + kgA);
    CP_COMMIT;

    for (int ch = 0; ch < 16; ch++) {
        if (ch < 15) {
            int kc = (ch + 1) * 32;
            int nb = (ch + 1) & 1;
            cp16(&Ah[nb][mA][kgA], g_xh + (size_t)(m0 + mA) * 512 + kc + kgA);
            cp16(&Al[nb][mA][kgA], g_xl + (size_t)(m0 + mA) * 512 + kc + kgA);
            cp16(&Bh[nb][mA][kgA], g_woTh + (size_t)mA * 512 + kc + kgA);
            cp16(&Bl[nb][mA][kgA], g_woTl + (size_t)mA * 512 + kc + kgA);
            CP_COMMIT;
            CP_WAIT1;
        } else {
            CP_WAIT0;
        }
        __syncthreads();
        int buf = ch & 1;

#pragma unroll
        for (int ks = 0; ks < 32; ks += 16) {
            uint32_t ah[4], al[4];
            {
                int r0 = wm * 16 + rsel;
                ldsm4(ah, (uint32_t)__cvta_generic_to_shared(&Ah[buf][r0][ks + csel]));
                ldsm4(al, (uint32_t)__cvta_generic_to_shared(&Al[buf][r0][ks + csel]));
            }
            uint32_t bh[2][4], bl[2][4];
#pragma unroll
            for (int p = 0; p < 2; p++) {
                int n0 = wn * 32 + p * 16 + rsel;
                ldsm4(bh[p], (uint32_t)__cvta_generic_to_shared(&Bh[buf][n0][ks + csel]));
                ldsm4(bl[p], (uint32_t)__cvta_generic_to_shared(&Bl[buf][n0][ks + csel]));
            }
#pragma unroll
            for (int nt = 0; nt < 4; nt++) {
                int p = nt >> 1, sub = nt & 1;
                uint32_t b0 = bh[p][sub], b1 = bh[p][sub + 2];
                uint32_t c0_ = bl[p][sub], c1_ = bl[p][sub + 2];
                mma_bf16(acc[nt], ah[0], ah[1], ah[2], ah[3], b0, b1);
                mma_bf16(acc[nt], ah[0], ah[1], ah[2], ah[3], c0_, c1_);
                mma_bf16(acc[nt], al[0], al[1], al[2], al[3], b0, b1);
            }
        }
        __syncthreads();
    }
#pragma unroll
    for (int nt = 0; nt < 4; nt++) {
        int r0 = m0 + wm * 16 + g;
        int c = wn * 32 + nt * 8 + 2 * tig;
        *(float2*)&g_Wh2[(size_t)r0 * 64 + c] = make_float2(acc[nt][0], acc[nt][1]);
        *(float2*)&g_Wh2[(size_t)(r0 + 8) * 64 + c] = make_float2(acc[nt][2], acc[nt][3]);
    }
}

// ===================== factorized GAT attention (1024 threads, 2 blocks/SM) =====================
// e[i,j] = leaky_relu(s_i + d_j): positive set is a suffix in d-sorted order.
__global__ __launch_bounds__(1024, 2) void attend_kernel(int layer, int rowsPerBlock,
                                                         const float* __restrict__ asrc,
                                                         const float* __restrict__ adst) {
    __shared__ float dv[512];
    __shared__ int   perm[512];
    __shared__ float ssrc[512];
    __shared__ float Ac[512];
    __shared__ float Bc[512];
    __shared__ float preB[65][65];   // [c][o], o=0..63 cols, o=64 scalar
    __shared__ float sufA[65][65];
    __shared__ float gsum[8][65];
    __shared__ float sAs[64], sAd[64];
    __shared__ int   Kv[512];

    const float* Wh = (layer == 1) ? g_Wh : g_Wh2;
    __nv_bfloat16* outh = (layer == 1) ? g_xh : g_zh;
    __nv_bfloat16* outl = (layer == 1) ? g_xl : g_zl;
    const int istride = (layer == 1) ? 512 : 64;
    const int aStride = (layer == 1) ? 64 : 0;
    const int doElu   = (layer == 1) ? 1 : 0;

    int tid = threadIdx.x;
    int h = blockIdx.x, b = blockIdx.y;
    int rStart = blockIdx.z * rowsPerBlock;
    const float* base = Wh + (size_t)b * 512 * istride + h * 64;
    size_t obase = (size_t)b * 512 * istride + h * 64;

    if (tid < 64) { sAs[tid] = asrc[h * aStride + tid]; sAd[tid] = adst[h * aStride + tid]; }
    __syncthreads();

    int warp = tid >> 5, l = tid & 31;
    for (int n = warp * 16; n < warp * 16 + 16; n++) {
        const float* row = base + (size_t)n * istride;
        float v0 = row[l], v1 = row[l + 32];
        float ps = v0 * sAs[l] + v1 * sAs[l + 32];
        float pd = v0 * sAd[l] + v1 * sAd[l + 32];
#pragma unroll
        for (int off = 16; off; off >>= 1) {
            ps += __shfl_xor_sync(0xffffffffu, ps, off);
            pd += __shfl_xor_sync(0xffffffffu, pd, off);
        }
        if (l == 0) { ssrc[n] = ps; dv[n] = pd; perm[n] = n; }
    }
    __syncthreads();

    // register-resident bitonic sort on tid<512 (shfl j<32, smem exchange j>=32)
    float key = (tid < 512) ? dv[tid] : 0.f;
    int   pm  = (tid < 512) ? perm[tid] : 0;
    for (int k = 2; k <= 512; k <<= 1) {
        for (int j = k >> 1; j > 0; j >>= 1) {
            if (j >= 32) {
                __syncthreads();
                if (tid < 512) { dv[tid] = key; perm[tid] = pm; }
                __syncthreads();
                if (tid < 512) {
                    float pk = dv[tid ^ j]; int pp = perm[tid ^ j];
                    bool up = ((tid & k) == 0);
                    bool iLower = ((tid & j) == 0);
                    bool wantMin = (up == iLower);
                    if (wantMin ? (pk < key) : (pk > key)) { key = pk; pm = pp; }
                }
            } else if (tid < 512) {
                float pk = __shfl_xor_sync(0xffffffffu, key, j);
                int   pp = __shfl_xor_sync(0xffffffffu, pm, j);
                bool up = ((tid & k) == 0);
                bool iLower = ((tid & j) == 0);
                bool wantMin = (up == iLower);
                if (wantMin ? (pk < key) : (pk > key)) { key = pk; pm = pp; }
            }
        }
    }
    __syncthreads();
    if (tid < 512) { dv[tid] = key; perm[tid] = pm; }
    __syncthreads();

    float dm = dv[511];
    if (tid < 512) {
        float d = key - dm;
        Ac[tid] = __expf(d);
        Bc[tid] = __expf(0.2f * d);
    }
    if (tid < 65) { preB[0][tid] = 0.f; sufA[64][tid] = 0.f; }
    __syncthreads();

    // chunk sums (64 chunks of 8, 65 "columns"; col 64 carries scalar sums)
    for (int it = tid; it < 64 * 65; it += 1024) {
        int c = it / 65;
        int o = it - c * 65;
        float sA = 0.f, sB = 0.f;
#pragma unroll
        for (int q = 0; q < 8; q++) {
            int j = c * 8 + q;
            float v = (o < 64) ? base[(size_t)perm[j] * istride + o] : 1.0f;
            sA += Ac[j] * v;
            sB += Bc[j] * v;
        }
        sufA[c][o] = sA;
        preB[c + 1][o] = sB;
    }
    __syncthreads();

    // two-level prefix scan of preB over c = 1..64
    for (int it = tid; it < 8 * 65; it += 1024) {
        int g = it / 65, o = it - g * 65;
        float run = 0.f;
#pragma unroll
        for (int k2 = 0; k2 < 8; k2++) {
            int c = g * 8 + 1 + k2;
            run += preB[c][o];
            preB[c][o] = run;
        }
        gsum[g][o] = run;
    }
    __syncthreads();
    if (tid < 65) {
        int o = tid;
        float run = 0.f;
#pragma unroll
        for (int g = 0; g < 8; g++) { float t = gsum[g][o]; gsum[g][o] = run; run += t; }
    }
    __syncthreads();
    for (int it = tid; it < 8 * 65; it += 1024) {
        int g = it / 65, o = it - g * 65;
        float add = gsum[g][o];
#pragma unroll
        for (int k2 = 0; k2 < 8; k2++) preB[g * 8 + 1 + k2][o] += add;
    }
    __syncthreads();

    // two-level suffix scan of sufA over c = 63..0
    for (int it = tid; it < 8 * 65; it += 1024) {
        int g = it / 65, o = it - g * 65;
        float run = 0.f;
#pragma unroll
        for (int k2 = 7; k2 >= 0; k2--) {
            int c = g * 8 + k2;
            run += sufA[c][o];
            sufA[c][o] = run;
        }
        gsum[g][o] = run;
    }
    __syncthreads();
    if (tid < 65) {
        int o = tid;
        float run = 0.f;
#pragma unroll
        for (int g = 7; g >= 0; g--) { float t = gsum[g][o]; gsum[g][o] = run; run += t; }
    }
    __syncthreads();
    for (int it = tid; it < 8 * 65; it += 1024) {
        int g = it / 65, o = it - g * 65;
        float add = gsum[g][o];
#pragma unroll
        for (int k2 = 0; k2 < 8; k2++) sufA[g * 8 + k2][o] += add;
    }
    __syncthreads();

    if (tid < rowsPerBlock) {
        float negs = -ssrc[rStart + tid];
        int lo = 0, hi = 512;
        while (lo < hi) { int mid = (lo + hi) >> 1; if (dv[mid] <= negs) lo = mid + 1; else hi = mid; }
        Kv[tid] = lo;
    }
    __syncthreads();

    // row outputs: warp per row, strided over 32 warps; emit bf16 h/l split
    for (int ni = warp; ni < rowsPerBlock; ni += 32) {
        int n = rStart + ni;
        int K = Kv[ni];
        int cc = K >> 3;
        int ccp = (cc < 64) ? cc + 1 : 64;
        float t = ssrc[n] + dm;
        float m = fmaxf(t, 0.2f * t);
        float c1 = __expf(t - m), c2 = __expf(0.2f * t - m);

        float p0 = preB[cc][l],  p1 = preB[cc][l + 32],  pS = preB[cc][64];
        float s0 = sufA[ccp][l], s1 = sufA[ccp][l + 32], sS = sufA[ccp][64];
#pragma unroll
        for (int q = 0; q < 8; q++) {
            int j = cc * 8 + q;
            if (j < 512) {
                const float* prow = base + (size_t)perm[j] * istride;
                float v0 = prow[l], v1 = prow[l + 32];
                if (j < K) {
                    float wgt = Bc[j];
                    p0 += wgt * v0; p1 += wgt * v1; pS += wgt;
                } else {
                    float wgt = Ac[j];
                    s0 += wgt * v0; s1 += wgt * v1; sS += wgt;
                }
            }
        }
        float inv = 1.f / (c1 * sS + c2 * pS);
        float r0 = (c1 * s0 + c2 * p0) * inv;
        float r1 = (c1 * s1 + c2 * p1) * inv;
        if (doElu) {
            r0 = (r0 > 0.f) ? r0 : (__expf(r0) - 1.f);
            r1 = (r1 > 0.f) ? r1 : (__expf(r1) - 1.f);
        }
        size_t oidx = obase + (size_t)n * istride;
        __nv_bfloat16 h0, l0, h1, l1;
        split_bf16(r0, h0, l0);
        split_bf16(r1, h1, l1);
        outh[oidx + l] = h0;      outl[oidx + l] = l0;
        outh[oidx + l + 32] = h1; outl[oidx + l + 32] = l1;
    }
}

// ===================== fc1 (mma): z(32x32768) @ fc1_w(32768x256), split-K x128 =====================
__global__ __launch_bounds__(256) void fc1_mma(const float* __restrict__ w) {
    __shared__ __align__(16) __nv_bfloat16 Ash[32][40], Asl[32][40];
    __shared__ __align__(16) __nv_bfloat16 Bh[256][40], Bl[256][40];
    int tid = threadIdx.x;
    int kb0 = blockIdx.x * 256;
    int wr = tid >> 5, lane = tid & 31;
    int g = lane >> 2, tig = lane & 3;
    int rsel, csel; ldsm_sel(lane, rsel, csel);

    float acc[2][4][4];
#pragma unroll
    for (int a = 0; a < 2; a++)
#pragma unroll
        for (int b = 0; b < 4; b++)
#pragma unroll
            for (int c = 0; c < 4; c++) acc[a][b][c] = 0.f;

    for (int ch = 0; ch < 8; ch++) {
        int kb = kb0 + ch * 32;
        if (ch) __syncthreads();
        {
            int idx = tid & 127;
            int m = idx >> 2, kg = (idx & 3) * 8;
            if (tid < 128)
                cp16(&Ash[m][kg], g_zh + (size_t)m * 32768 + kb + kg);
            else
                cp16(&Asl[m][kg], g_zl + (size_t)m * 32768 + kb + kg);
        }
        CP_COMMIT;
#pragma unroll
        for (int r = 0; r < 8; r++) {
            int idx = tid + r * 256;
            int k = idx >> 6, n4 = (idx & 63) * 4;
            float4 v = *(const float4*)(w + (size_t)(kb + k) * 256 + n4);
            __nv_bfloat16 h, l2;
            split_bf16(v.x, h, l2); Bh[n4 + 0][k] = h; Bl[n4 + 0][k] = l2;
            split_bf16(v.y, h, l2); Bh[n4 + 1][k] = h; Bl[n4 + 1][k] = l2;
            split_bf16(v.z, h, l2); Bh[n4 + 2][k] = h; Bl[n4 + 2][k] = l2;
            split_bf16(v.w, h, l2); Bh[n4 + 3][k] = h; Bl[n4 + 3][k] = l2;
        }
        CP_WAIT0;
        __syncthreads();

#pragma unroll
        for (int ks = 0; ks < 32; ks += 16) {
            uint32_t ah[2][4], al[2][4];
#pragma unroll
            for (int mt = 0; mt < 2; mt++) {
                int r0 = mt * 16 + rsel;
                ldsm4(ah[mt], (uint32_t)__cvta_generic_to_shared(&Ash[r0][ks + csel]));
                ldsm4(al[mt], (uint32_t)__cvta_generic_to_shared(&Asl[r0][ks + csel]));
            }
            uint32_t bh[2][4], bl[2][4];
#pragma unroll
            for (int p = 0; p < 2; p++) {
                int n0 = wr * 32 + p * 16 + rsel;
                ldsm4(bh[p], (uint32_t)__cvta_generic_to_shared(&Bh[n0][ks + csel]));
                ldsm4(bl[p], (uint32_t)__cvta_generic_to_shared(&Bl[n0][ks + csel]));
            }
#pragma unroll
            for (int nt = 0; nt < 4; nt++) {
                int p = nt >> 1, sub = nt & 1;
                uint32_t b0 = bh[p][sub], b1 = bh[p][sub + 2];
                uint32_t c0_ = bl[p][sub], c1_ = bl[p][sub + 2];
#pragma unroll
                for (int mt = 0; mt < 2; mt++) {
                    mma_bf16(acc[mt][nt], ah[mt][0], ah[mt][1], ah[mt][2], ah[mt][3], b0, b1);
                    mma_bf16(acc[mt][nt], ah[mt][0], ah[mt][1], ah[mt][2], ah[mt][3], c0_, c1_);
                    mma_bf16(acc[mt][nt], al[mt][0], al[mt][1], al[mt][2], al[mt][3], b0, b1);
                }
            }
        }
    }
#pragma unroll
    for (int mt = 0; mt < 2; mt++)
#pragma unroll
        for (int nt = 0; nt < 4; nt++) {
            int row = mt * 16 + g;
            int cb = wr * 32 + nt * 8 + 2 * tig;
            *(float2*)&g_part[(size_t)blockIdx.x * 8192 + row * 256 + cb] =
                make_float2(acc[mt][nt][0], acc[mt][nt][1]);
            *(float2*)&g_part[(size_t)blockIdx.x * 8192 + (row + 8) * 256 + cb] =
                make_float2(acc[mt][nt][2], acc[mt][nt][3]);
        }
}

__global__ void fc1_reduce1() {
    int sg = blockIdx.x >> 5;                      // 0..7
    int idx = (blockIdx.x & 31) * 256 + threadIdx.x;
    float s = 0.f;
#pragma unroll
    for (int q = 0; q < 16; q++) s += g_part[(size_t)(sg * 16 + q) * 8192 + idx];
    g_part2[sg * 8192 + idx] = s;
}

__global__ void fc1_reduce2(const float* __restrict__ bias) {
    int idx = blockIdx.x * 256 + threadIdx.x;      // 0..8191
    float s = bias[idx & 255];
#pragma unroll
    for (int q = 0; q < 8; q++) s += g_part2[q * 8192 + idx];
    g_z1[idx] = fmaxf(s, 0.f);
}

__global__ __launch_bounds__(256) void fc2_kernel(const float* __restrict__ w,
                                                  const float* __restrict__ bias) {
    __shared__ float zs[32 * 260];
    int tid = threadIdx.x;
    for (int i = tid; i < 8192; i += 256) zs[(i >> 8) * 260 + (i & 255)] = g_z1[i];
    __syncthreads();
    int c = blockIdx.x * 8 + (tid & 7);
    int r = tid >> 3;
    float acc = bias[c];
#pragma unroll 8
    for (int k = 0; k < 256; k++) acc += zs[r * 260 + k] * w[k * 256 + c];
    g_z2[r * 256 + c] = fmaxf(acc, 0.f);
}

__global__ void fc3_kernel(const float* __restrict__ w, const float* __restrict__ bias,
                           float* __restrict__ outp) {
    int tid = threadIdx.x;       // 256 threads = 128 (r,a) pairs x 2-way k split
    int p = tid >> 1, half = tid & 1;
    int r = p >> 2, a = p & 3;
    float acc = 0.f;
    int kb = half * 128;
#pragma unroll 8
    for (int k = 0; k < 128; k++) acc += g_z2[r * 256 + kb + k] * w[(kb + k) * 4 + a];
    acc += __shfl_xor_sync(0xffffffffu, acc, 1);
    if (half == 0) outp[r * 4 + a] = tanhf(acc + bias[a]);   // MAX_ACTION = 1.0
}

// ===================== launch =====================
extern "C" void kernel_launch(void* const* d_in, const int* in_sizes, int n_in,
                              void* d_out, int out_size) {
    const float* state     = (const float*)d_in[0];
    const float* W_heads   = (const float*)d_in[1];
    const float* a_src     = (const float*)d_in[2];
    const float* a_dst     = (const float*)d_in[3];
    const float* W_out     = (const float*)d_in[4];
    const float* a_out_src = (const float*)d_in[5];
    const float* a_out_dst = (const float*)d_in[6];
    const float* fc1_w     = (const float*)d_in[7];
    const float* fc1_b     = (const float*)d_in[8];
    const float* fc2_w     = (const float*)d_in[9];
    const float* fc2_b     = (const float*)d_in[10];
    const float* fc3_w     = (const float*)d_in[11];
    const float* fc3_b     = (const float*)d_in[12];
    float* out = (float*)d_out;

    prep_split<<<4352, 256>>>(state, W_heads, W_out);
    gemm1_mma<<<dim3(4, 128), 256>>>();
    attend_kernel<<<dim3(8, 32, 1), 1024>>>(1, 512, a_src, a_dst);         // 256 blocks
    gemm2_mma<<<256, 256>>>();
    attend_kernel<<<dim3(1, 32, 4), 1024>>>(2, 128, a_out_src, a_out_dst); // 128 blocks
    fc1_mma<<<128, 256>>>(fc1_w);
    fc1_reduce1<<<256, 256>>>();
    fc1_reduce2<<<32, 256>>>(fc1_b);
    fc2_kernel<<<32, 256>>>(fc2_w, fc2_b);
    fc3_kernel<<<1, 256>>>(fc3_w, fc3_b, out);
}